// round 10
// baseline (speedup 1.0000x reference)
#include <cuda_runtime.h>
#include <cuda_bf16.h>
#include <math.h>
#include <stdint.h>

#define B 64
#define S 2048
#define E 1024
#define H 512
#define EMBD 256
#define V 50257
#define MTOT (B*S)

#define OUT_HT ((size_t)B*V)
#define OUT_CT (OUT_HT + (size_t)B*H)

// two-digit base-254 int8: x = SA*(254*qhi + qlo), SA=2^-12; w: SB=2^-18
// e = SA*SB*(254^2*hh + 254*cx + ll)
#define W_HH (64516.0f/1073741824.0f)
#define W_CX (254.0f/1073741824.0f)
#define W_LL (1.0f/1073741824.0f)

// ---------------- device scratch (no allocations allowed) ----------------
__device__ float g_ws_app[B*H];
__device__ float g_energy16[16][MTOT];   // per-n-tile energy partials
__device__ float g_attn[MTOT];
__device__ float g_context[B*E];
__device__ float g_embed[B*EMBD];
__device__ float g_gates[B*4*H];
__device__ float g_logits[(size_t)B*V];
__device__ float g_pgen[B];

__device__ int8_t g_enc_qhi[(size_t)MTOT*E];
__device__ int8_t g_enc_qlo[(size_t)MTOT*E];
__device__ int8_t g_w_qhi[H*E];
__device__ int8_t g_w_qlo[H*E];

__device__ __forceinline__ float sigf(float x){ return 1.f/(1.f+__expf(-x)); }

// ======================= portable PTX helpers =============================
__device__ __forceinline__ uint32_t smem_u32(const void* p){
    uint32_t a;
    asm("{ .reg .u64 t; cvta.to.shared.u64 t, %1; cvt.u32.u64 %0, t; }" : "=r"(a) : "l"(p));
    return a;
}
__device__ __forceinline__ void cp16(uint32_t dst, const void* src){
    asm volatile("cp.async.cg.shared.global [%0], [%1], 16;" :: "r"(dst), "l"(src));
}
__device__ __forceinline__ void cp_commit(){ asm volatile("cp.async.commit_group;" ::: "memory"); }
__device__ __forceinline__ void cp_wait0(){ asm volatile("cp.async.wait_group 0;" ::: "memory"); }

__device__ __forceinline__ void ldsm4(uint32_t* r, uint32_t addr){
    asm volatile("ldmatrix.sync.aligned.m8n8.x4.shared.b16 {%0,%1,%2,%3}, [%4];"
        : "=r"(r[0]), "=r"(r[1]), "=r"(r[2]), "=r"(r[3]) : "r"(addr));
}
__device__ __forceinline__ void mma_s8(int* c, const uint32_t* a, uint32_t b0, uint32_t b1){
    asm volatile("mma.sync.aligned.m16n8k32.row.col.s32.s8.s8.s32 "
        "{%0,%1,%2,%3}, {%4,%5,%6,%7}, {%8,%9}, {%0,%1,%2,%3};"
        : "+r"(c[0]), "+r"(c[1]), "+r"(c[2]), "+r"(c[3])
        : "r"(a[0]), "r"(a[1]), "r"(a[2]), "r"(a[3]), "r"(b0), "r"(b1));
}

__device__ __forceinline__ uint32_t pack4(int a, int b, int c, int d){
    return (uint32_t)(a & 0xff) | ((uint32_t)(b & 0xff) << 8) |
           ((uint32_t)(c & 0xff) << 16) | ((uint32_t)(d & 0xff) << 24);
}

// ---------------- two-digit int8 quantization kernels ---------------------
__global__ void conv_enc_q(const float* __restrict__ src){
    size_t base = ((size_t)blockIdx.x*256 + threadIdx.x)*8;
    float4 v0 = *(const float4*)(src + base);
    float4 v1 = *(const float4*)(src + base + 4);
    float xs[8] = {v0.x,v0.y,v0.z,v0.w,v1.x,v1.y,v1.z,v1.w};
    int ih[8], il[8];
    #pragma unroll
    for (int k = 0; k < 8; k++){
        int h = __float2int_rn(xs[k]*16.125984251968504f);   // 4096/254
        h = max(-127, min(127, h));
        float r = fmaf((float)h, -0.062011718750f, xs[k]);   // 254/4096
        int l = __float2int_rn(r*4096.f);
        l = max(-127, min(127, l));
        ih[k] = h; il[k] = l;
    }
    uint2 hw = make_uint2(pack4(ih[0],ih[1],ih[2],ih[3]), pack4(ih[4],ih[5],ih[6],ih[7]));
    uint2 lw = make_uint2(pack4(il[0],il[1],il[2],il[3]), pack4(il[4],il[5],il[6],il[7]));
    *(uint2*)(g_enc_qhi + base) = hw;
    *(uint2*)(g_enc_qlo + base) = lw;
}
__global__ void conv_w_q(const float* __restrict__ src){
    int base = (blockIdx.x*256 + threadIdx.x)*4;
    float4 v = *(const float4*)(src + base);
    float xs[4] = {v.x, v.y, v.z, v.w};
    int ih[4], il[4];
    #pragma unroll
    for (int k = 0; k < 4; k++){
        int h = __float2int_rn(xs[k]*1032.0629921259842f);    // 262144/254
        h = max(-127, min(127, h));
        float r = fmaf((float)h, -9.68933105468750e-4f, xs[k]); // 254/262144
        int l = __float2int_rn(r*262144.f);
        l = max(-127, min(127, l));
        ih[k] = h; il[k] = l;
    }
    *(uint32_t*)(g_w_qhi + base) = pack4(ih[0],ih[1],ih[2],ih[3]);
    *(uint32_t*)(g_w_qlo + base) = pack4(il[0],il[1],il[2],il[3]);
}

// ---------------- zero context (accumulated via atomics) -----------------
__global__ void zero_kernel(){
    int i = blockIdx.x*blockDim.x + threadIdx.x;
    if (i < B*E) g_context[i] = 0.f;
}

// ---------------- ws_app[b,n] = h0[b]·ws_w[n] + ws_b[n] + wh_b[n] --------
__global__ void wsapp_kernel(const float* __restrict__ h0,
                             const float* __restrict__ ws_w,
                             const float* __restrict__ ws_b,
                             const float* __restrict__ wh_b){
    int b = blockIdx.x;
    int warp = threadIdx.x >> 5, lane = threadIdx.x & 31;
    int n = blockIdx.y * 8 + warp;
    const float* wrow = ws_w + (size_t)n*H;
    const float* hrow = h0 + b*H;
    float acc = 0.f;
    for (int k = lane; k < H; k += 32) acc += hrow[k]*wrow[k];
    #pragma unroll
    for (int o = 16; o > 0; o >>= 1) acc += __shfl_xor_sync(0xffffffffu, acc, o);
    if (lane == 0) g_ws_app[b*H + n] = acc + ws_b[n] + wh_b[n];
}

// ---------------- embedding lookup ---------------------------------------
__global__ void embed_kernel(const int* __restrict__ dec_input,
                             const float* __restrict__ table){
    int b = blockIdx.x, t = threadIdx.x;
    g_embed[b*EMBD + t] = table[(size_t)dec_input[b]*EMBD + t];
}

// ---------------- int8 exact 4-product energy GEMM -----------------------
#define MT 128
#define NTILE 32
#define KC 64
#define NCH (E/KC)                 // 16
#define RB 80                      // row stride bytes (64 data + 16 pad)
#define A_ARR (128*RB)             // 10240
#define B_ARR (32*RB)              // 2560
#define STG (2*A_ARR + 2*B_ARR)    // 25600
#define WS_OFF (2*STG)             // 51200
#define V_OFF  (WS_OFF + 128)
#define RED_OFF (V_OFF + 128)
#define EN_SMEM (RED_OFF + 1024)

__global__ __launch_bounds__(256, 2) void energy_mma(const float* __restrict__ attn_v){
    extern __shared__ char sm[];
    const int tid  = threadIdx.x;
    const int lane = tid & 31, wid = tid >> 5;
    const int wm = wid & 3;            // 4 M-groups of 32 rows
    const int wn = wid >> 2;           // 2 N-groups of 16 cols
    const int n0 = blockIdx.x * NTILE; // fast grid dim: L2 reuse of A
    const int m0 = blockIdx.y * MT;
    const int b  = m0 >> 11;

    float* wsP = (float*)(sm + WS_OFF);
    float* vP  = (float*)(sm + V_OFF);
    float* red = (float*)(sm + RED_OFF);
    if (tid < NTILE){
        wsP[tid] = g_ws_app[b*H + n0 + tid];
        vP[tid]  = attn_v[n0 + tid];
    }
    const uint32_t smb = smem_u32(sm);

    const int8_t* Ahi_g = g_enc_qhi + (size_t)m0*E;
    const int8_t* Alo_g = g_enc_qlo + (size_t)m0*E;
    const int8_t* Bhi_g = g_w_qhi  + (size_t)n0*E;
    const int8_t* Blo_g = g_w_qlo  + (size_t)n0*E;

    auto loadAB = [&](int i){
        uint32_t stg = smb + (i&1)*STG;
        int k0 = i*KC;
        #pragma unroll
        for (int it = 0; it < 5; it++){
            int f = tid + it*256;               // 0..1279
            if (f < 1024){                       // A: hi then lo
                int arr = f >> 9, idx = f & 511;
                int r = idx >> 2, j = idx & 3;
                cp16(stg + arr*A_ARR + r*RB + j*16,
                     (arr ? Alo_g : Ahi_g) + (size_t)r*E + k0 + j*16);
            } else {                             // B: hi then lo (256 chunks)
                int g2 = f - 1024;
                int arr = g2 >> 7, idx = g2 & 127;
                int r = idx >> 2, j = idx & 3;
                cp16(stg + 2*A_ARR + arr*B_ARR + r*RB + j*16,
                     (arr ? Blo_g : Bhi_g) + (size_t)r*E + k0 + j*16);
            }
        }
        cp_commit();
    };

    int hh[2][2][4], cx[2][2][4], ll[2][2][4];
    #pragma unroll
    for (int t = 0; t < 2; t++)
        #pragma unroll
        for (int j = 0; j < 2; j++)
            #pragma unroll
            for (int q = 0; q < 4; q++){ hh[t][j][q] = 0; cx[t][j][q] = 0; ll[t][j][q] = 0; }

    loadAB(0);

    for (int i = 0; i < NCH; i++){
        cp_wait0();
        __syncthreads();
        if (i + 1 < NCH) loadAB(i+1);

        const uint32_t stg = smb + (i&1)*STG;
        #pragma unroll
        for (int ks = 0; ks < 2; ks++){
            const int kb = ks*32;
            uint32_t ah[2][4], al[2][4];
            #pragma unroll
            for (int t = 0; t < 2; t++){
                uint32_t off = stg + (uint32_t)(wm*32 + t*16 + (lane & 15))*RB
                                   + (lane >> 4)*16 + kb;
                ldsm4(ah[t], off);
                ldsm4(al[t], off + A_ARR);
            }
            uint32_t bh[4], bl[4];
            {
                uint32_t off = stg + 2*A_ARR
                             + (uint32_t)(wn*16 + ((lane >> 4) & 1)*8 + (lane & 7))*RB
                             + ((lane >> 3) & 1)*16 + kb;
                ldsm4(bh, off);
                ldsm4(bl, off + B_ARR);
            }
            #pragma unroll
            for (int t = 0; t < 2; t++)
                #pragma unroll
                for (int j = 0; j < 2; j++){
                    const int s = j*2;
                    mma_s8(hh[t][j], ah[t], bh[s], bh[s+1]);
                    mma_s8(cx[t][j], ah[t], bl[s], bl[s+1]);
                    mma_s8(cx[t][j], al[t], bh[s], bh[s+1]);
                    mma_s8(ll[t][j], al[t], bl[s], bl[s+1]);
                }
        }
    }

    // epilogue: combine digits, tanh, dot attn_v
    float p4[4] = {0.f, 0.f, 0.f, 0.f};
    #pragma unroll
    for (int t = 0; t < 2; t++)
        #pragma unroll
        for (int j = 0; j < 2; j++)
            #pragma unroll
            for (int q = 0; q < 4; q++){
                int nloc = wn*16 + j*8 + (lane & 3)*2 + (q & 1);
                float val = fmaf(W_HH, (float)hh[t][j][q],
                            fmaf(W_CX, (float)cx[t][j][q],
                            fmaf(W_LL, (float)ll[t][j][q], wsP[nloc])));
                p4[t*2 + (q >> 1)] += tanhf(val) * vP[nloc];
            }
    #pragma unroll
    for (int q = 0; q < 4; q++){
        p4[q] += __shfl_xor_sync(0xffffffffu, p4[q], 1);
        p4[q] += __shfl_xor_sync(0xffffffffu, p4[q], 2);
    }
    if ((lane & 3) == 0){
        int r0 = wm*32 + (lane >> 2);
        red[wn*128 + r0]      = p4[0];
        red[wn*128 + r0 + 8]  = p4[1];
        red[wn*128 + r0 + 16] = p4[2];
        red[wn*128 + r0 + 24] = p4[3];
    }
    __syncthreads();
    if (tid < 128)
        g_energy16[blockIdx.x][m0 + tid] = red[tid] + red[128 + tid];
}

// ---------------- softmax over S per batch (combines 16 partials) --------
__global__ void attn_softmax(){
    const int b = blockIdx.x, t = threadIdx.x;   // 256 threads, 8 elems/thread
    __shared__ float red[8];
    float ev[8];
    float m = -1e30f;
    #pragma unroll
    for (int q = 0; q < 8; q++){
        int idx = b*S + q*256 + t;
        float v = 0.f;
        #pragma unroll
        for (int k = 0; k < 16; k++) v += g_energy16[k][idx];
        ev[q] = v;
        m = fmaxf(m, v);
    }
    #pragma unroll
    for (int o = 16; o > 0; o >>= 1) m = fmaxf(m, __shfl_xor_sync(0xffffffffu, m, o));
    if ((t & 31) == 0) red[t >> 5] = m;
    __syncthreads();
    if (t == 0){ float mm = red[0]; for (int i = 1; i < 8; i++) mm = fmaxf(mm, red[i]); red[0] = mm; }
    __syncthreads();
    m = red[0];
    __syncthreads();
    float s = 0.f;
    #pragma unroll
    for (int q = 0; q < 8; q++){ ev[q] = __expf(ev[q]-m); s += ev[q]; }
    #pragma unroll
    for (int o = 16; o > 0; o >>= 1) s += __shfl_xor_sync(0xffffffffu, s, o);
    if ((t & 31) == 0) red[t >> 5] = s;
    __syncthreads();
    if (t == 0){ float ss = 0.f; for (int i = 0; i < 8; i++) ss += red[i]; red[0] = ss; }
    __syncthreads();
    float inv = 1.f / red[0];
    #pragma unroll
    for (int q = 0; q < 8; q++) g_attn[b*S + q*256 + t] = ev[q] * inv;
}

// ---------------- context[b,e] = sum_s attn[b,s]*enc[b,s,e] --------------
__global__ void context_kernel(const float* __restrict__ enc){
    const int b = blockIdx.x, ec = blockIdx.y, sc = blockIdx.z;
    __shared__ float a_s[512];
    const int t = threadIdx.x;
    for (int i = t; i < 512; i += 256) a_s[i] = g_attn[b*S + sc*512 + i];
    __syncthreads();
    const int e = ec*256 + t;
    const float* base = enc + ((size_t)b*S + sc*512)*E + e;
    float acc = 0.f;
    #pragma unroll 4
    for (int s = 0; s < 512; s++) acc = fmaf(a_s[s], base[(size_t)s*E], acc);
    atomicAdd(&g_context[b*E + e], acc);
}

// ---------------- LSTM gates GEMM ----------------------------------------
__global__ __launch_bounds__(256) void gates_gemm(
        const float* __restrict__ h0,
        const float* __restrict__ w_ih,
        const float* __restrict__ w_hh,
        const float* __restrict__ b_ih,
        const float* __restrict__ b_hh){
    __shared__ float Xs[16][65];
    __shared__ float Ws[16][65];
    const int n0 = blockIdx.x * 64;
    const int tid = threadIdx.x;
    const int tx = tid & 15, ty = tid >> 4;
    float acc[4][4];
    #pragma unroll
    for (int i = 0; i < 4; i++)
        #pragma unroll
        for (int j = 0; j < 4; j++) acc[i][j] = 0.f;

    for (int k0 = 0; k0 < 1792; k0 += 16) {
        for (int i = tid; i < 64*16; i += 256){
            int m = i >> 4, kk = i & 15, k = k0 + kk;
            float xv;
            if (k < E)            xv = g_context[m*E + k];
            else if (k < E+EMBD)  xv = g_embed[m*EMBD + (k - E)];
            else                  xv = h0[m*H + (k - E - EMBD)];
            Xs[kk][m] = xv;
        }
        for (int i = tid; i < 64*16; i += 256){
            int nn = i >> 4, kk = i & 15, k = k0 + kk, n = n0 + nn;
            float wv = (k < E+EMBD) ? w_ih[(size_t)n*(E+EMBD) + k]
                                    : w_hh[(size_t)n*H + (k - E - EMBD)];
            Ws[kk][nn] = wv;
        }
        __syncthreads();
        #pragma unroll
        for (int kk = 0; kk < 16; kk++){
            float ra[4], rb[4];
            #pragma unroll
            for (int i = 0; i < 4; i++) ra[i] = Xs[kk][ty*4+i];
            #pragma unroll
            for (int j = 0; j < 4; j++) rb[j] = Ws[kk][tx*4+j];
            #pragma unroll
            for (int i = 0; i < 4; i++)
                #pragma unroll
                for (int j = 0; j < 4; j++) acc[i][j] = fmaf(ra[i], rb[j], acc[i][j]);
        }
        __syncthreads();
    }
    #pragma unroll
    for (int i = 0; i < 4; i++)
        #pragma unroll
        for (int j = 0; j < 4; j++){
            int m = ty*4+i, n = n0 + tx*4+j;
            g_gates[m*(4*H) + n] = acc[i][j] + b_ih[n] + b_hh[n];
        }
}

// ---------------- LSTM pointwise -----------------------------------------
__global__ void lstm_kernel(const float* __restrict__ c0, float* __restrict__ out){
    const int b = blockIdx.x, h = threadIdx.x;
    const float* g = g_gates + b*(4*H);
    float ig = sigf(g[h]);
    float fg = sigf(g[H + h]);
    float gg = tanhf(g[2*H + h]);
    float og = sigf(g[3*H + h]);
    float c  = fg * c0[b*H + h] + ig * gg;
    float ht = og * tanhf(c);
    out[OUT_HT + b*H + h] = ht;
    out[OUT_CT + b*H + h] = c;
}

// ---------------- logits = h_t @ v_w.T + v_b -----------------------------
__global__ __launch_bounds__(256) void logits_gemm(
        const float* __restrict__ ht,
        const float* __restrict__ v_w,
        const float* __restrict__ v_b){
    __shared__ float Hs[32][64];
    __shared__ float Vs[32][128];
    const int v0 = blockIdx.x * 128;
    const int tid = threadIdx.x;
    const int tx = tid & 15, ty = tid >> 4;
    float acc[4][8];
    #pragma unroll
    for (int i = 0; i < 4; i++)
        #pragma unroll
        for (int j = 0; j < 8; j++) acc[i][j] = 0.f;

    for (int k0 = 0; k0 < H; k0 += 32) {
        for (int fl = tid; fl < 512; fl += 256){
            int m = fl >> 3, kq = (fl & 7) << 2;
            float4 hv = *(const float4*)(ht + (size_t)m*H + k0 + kq);
            Hs[kq+0][m]=hv.x; Hs[kq+1][m]=hv.y; Hs[kq+2][m]=hv.z; Hs[kq+3][m]=hv.w;
        }
        for (int fl = tid; fl < 1024; fl += 256){
            int vr = fl >> 3, kq = (fl & 7) << 2;
            int v = v0 + vr;
            float4 wv = make_float4(0.f,0.f,0.f,0.f);
            if (v < V) wv = *(const float4*)(v_w + (size_t)v*H + k0 + kq);
            Vs[kq+0][vr]=wv.x; Vs[kq+1][vr]=wv.y; Vs[kq+2][vr]=wv.z; Vs[kq+3][vr]=wv.w;
        }
        __syncthreads();
        #pragma unroll
        for (int kk = 0; kk < 32; kk++){
            float4 a0 = *(const float4*)(&Hs[kk][ty*4]);
            float4 b0 = *(const float4*)(&Vs[kk][tx*8]);
            float4 b1 = *(const float4*)(&Vs[kk][tx*8+4]);
            float ra[4] = {a0.x,a0.y,a0.z,a0.w};
            float rb[8] = {b0.x,b0.y,b0.z,b0.w,b1.x,b1.y,b1.z,b1.w};
            #pragma unroll
            for (int i = 0; i < 4; i++)
                #pragma unroll
                for (int j = 0; j < 8; j++) acc[i][j] = fmaf(ra[i], rb[j], acc[i][j]);
        }
        __syncthreads();
    }
    #pragma unroll
    for (int i = 0; i < 4; i++)
        #pragma unroll
        for (int j = 0; j < 8; j++){
            int m = ty*4+i, v = v0 + tx*8+j;
            if (v < V) g_logits[(size_t)m*V + v] = acc[i][j] + v_b[v];
        }
}

// ---------------- p_gen ---------------------------------------------------
__global__ void pgen_kernel(const float* __restrict__ ht,
                            const float* __restrict__ wh_vec,
                            const float* __restrict__ ws_vec,
                            const float* __restrict__ wx_vec){
    const int b = blockIdx.x, t = threadIdx.x;
    __shared__ float red[8];
    float acc = 0.f;
    for (int i = t; i < E;    i += 256) acc += g_context[b*E + i]   * wh_vec[i];
    for (int i = t; i < H;    i += 256) acc += ht[b*H + i]          * ws_vec[i];
    for (int i = t; i < EMBD; i += 256) acc += g_embed[b*EMBD + i]  * wx_vec[i];
    #pragma unroll
    for (int o = 16; o > 0; o >>= 1) acc += __shfl_xor_sync(0xffffffffu, acc, o);
    if ((t & 31) == 0) red[t >> 5] = acc;
    __syncthreads();
    if (t == 0){
        float s = 0.f;
        for (int i = 0; i < 8; i++) s += red[i];
        g_pgen[b] = sigf(s);
    }
}

// ---------------- vocab softmax * p_gen -> out ---------------------------
__global__ void vocab_out_kernel(float* __restrict__ out){
    const int b = blockIdx.x, t = threadIdx.x;
    __shared__ float red[16];
    const float* row = g_logits + (size_t)b*V;
    float m = -1e30f;
    for (int v = t; v < V; v += 512) m = fmaxf(m, row[v]);
    #pragma unroll
    for (int o = 16; o > 0; o >>= 1) m = fmaxf(m, __shfl_xor_sync(0xffffffffu, m, o));
    if ((t & 31) == 0) red[t >> 5] = m;
    __syncthreads();
    if (t == 0){ float mm = red[0]; for (int i = 1; i < 16; i++) mm = fmaxf(mm, red[i]); red[0] = mm; }
    __syncthreads();
    m = red[0];
    __syncthreads();
    float s = 0.f;
    for (int v = t; v < V; v += 512) s += __expf(row[v]-m);
    #pragma unroll
    for (int o = 16; o > 0; o >>= 1) s += __shfl_xor_sync(0xffffffffu, s, o);
    if ((t & 31) == 0) red[t >> 5] = s;
    __syncthreads();
    if (t == 0){ float ss = 0.f; for (int i = 0; i < 16; i++) ss += red[i]; red[0] = ss; }
    __syncthreads();
    const float scale = g_pgen[b] / red[0];
    for (int v = t; v < V; v += 512) out[(size_t)b*V + v] = __expf(row[v]-m) * scale;
}

// ---------------- copy-mechanism scatter ---------------------------------
__global__ void scatter_kernel(const int* __restrict__ enc_inputs,
                               float* __restrict__ out){
    const int idx = blockIdx.x*256 + threadIdx.x;
    if (idx >= MTOT) return;
    const int b = idx >> 11;
    const int tok = enc_inputs[idx];
    atomicAdd(&out[(size_t)b*V + tok], (1.f - g_pgen[b]) * g_attn[idx]);
}

// ---------------- launch --------------------------------------------------
extern "C" void kernel_launch(void* const* d_in, const int* in_sizes, int n_in,
                              void* d_out, int out_size) {
    const float* enc_out   = (const float*)d_in[0];
    const float* h0        = (const float*)d_in[1];
    const float* c0        = (const float*)d_in[2];
    const int*   dec_input = (const int*)  d_in[3];
    const int*   enc_inputs= (const int*)  d_in[4];
    const float* embed_tab = (const float*)d_in[5];
    const float* attn_wh_w = (const float*)d_in[6];
    const float* attn_wh_b = (const float*)d_in[7];
    const float* attn_ws_w = (const float*)d_in[8];
    const float* attn_ws_b = (const float*)d_in[9];
    const float* attn_v    = (const float*)d_in[10];
    const float* lstm_w_ih = (const float*)d_in[11];
    const float* lstm_w_hh = (const float*)d_in[12];
    const float* lstm_b_ih = (const float*)d_in[13];
    const float* lstm_b_hh = (const float*)d_in[14];
    const float* wh_vec    = (const float*)d_in[15];
    const float* ws_vec    = (const float*)d_in[16];
    const float* wx_vec    = (const float*)d_in[17];
    const float* v_w       = (const float*)d_in[18];
    const float* v_b       = (const float*)d_in[19];
    float* out = (float*)d_out;
    const float* ht = out + OUT_HT;

    static bool attr_set = false;
    if (!attr_set){
        cudaFuncSetAttribute(energy_mma, cudaFuncAttributeMaxDynamicSharedMemorySize, EN_SMEM);
        attr_set = true;
    }

    // energy_mma is the 4th launch (ncu capture slot)
    conv_w_q<<<512, 256>>>(attn_wh_w);
    wsapp_kernel<<<dim3(B, 64), 256>>>(h0, attn_ws_w, attn_ws_b, attn_wh_b);
    conv_enc_q<<<65536, 256>>>(enc_out);
    energy_mma<<<dim3(H/NTILE, MTOT/MT), 256, EN_SMEM>>>(attn_v);
    zero_kernel<<<256, 256>>>();
    embed_kernel<<<B, 256>>>(dec_input, embed_tab);
    attn_softmax<<<B, 256>>>();
    context_kernel<<<dim3(B, 4, 4), 256>>>(enc_out);
    gates_gemm<<<(4*H)/64, 256>>>(h0, lstm_w_ih, lstm_w_hh, lstm_b_ih, lstm_b_hh);
    lstm_kernel<<<B, 512>>>(c0, out);
    logits_gemm<<<(V + 127)/128, 256>>>(ht, v_w, v_b);
    pgen_kernel<<<B, 256>>>(ht, wh_vec, ws_vec, wx_vec);
    vocab_out_kernel<<<B, 512>>>(out);
    scatter_kernel<<<(MTOT + 255)/256, 256>>>(enc_inputs, out);
}

// round 11
// speedup vs baseline: 2.9144x; 2.9144x over previous
#include <cuda_runtime.h>
#include <cuda_fp16.h>
#include <math.h>
#include <stdint.h>

#define B 64
#define S 2048
#define E 1024
#define H 512
#define EMBD 256
#define V 50257
#define MTOT (B*S)

#define OUT_HT ((size_t)B*V)
#define OUT_CT (OUT_HT + (size_t)B*H)

// ---------------- device scratch (no allocations allowed) ----------------
__device__ float g_ws_app[B*H];        // h0@ws_w.T + ws_b + wh_b
__device__ float g_energy4[4][MTOT];   // per-n-block energy partials
__device__ float g_attn[MTOT];
__device__ float g_context[B*E];
__device__ float g_embed[B*EMBD];
__device__ float g_gates[B*4*H];
__device__ float g_logits[(size_t)B*V];
__device__ float g_pgen[B];

// single-fp16 copy of attn_wh_w (enc_out split to fp16 hi/lo in-kernel)
__device__ __half g_w_h[H*E];

__device__ __forceinline__ float sigf(float x){ return 1.f/(1.f+__expf(-x)); }

// ======================= portable PTX helpers =============================
__device__ __forceinline__ uint32_t smem_u32(const void* p){
    uint32_t a;
    asm("{ .reg .u64 t; cvta.to.shared.u64 t, %1; cvt.u32.u64 %0, t; }" : "=r"(a) : "l"(p));
    return a;
}
__device__ __forceinline__ void cp16(uint32_t dst, const void* src){
    asm volatile("cp.async.cg.shared.global [%0], [%1], 16;" :: "r"(dst), "l"(src));
}
__device__ __forceinline__ void cp_commit(){ asm volatile("cp.async.commit_group;" ::: "memory"); }
__device__ __forceinline__ void cp_wait0(){ asm volatile("cp.async.wait_group 0;" ::: "memory"); }

__device__ __forceinline__ void ldsm4(uint32_t* r, uint32_t addr){
    asm volatile("ldmatrix.sync.aligned.m8n8.x4.shared.b16 {%0,%1,%2,%3}, [%4];"
        : "=r"(r[0]), "=r"(r[1]), "=r"(r[2]), "=r"(r[3]) : "r"(addr));
}
__device__ __forceinline__ void mma_f16(float* c, const uint32_t* a, uint32_t b0, uint32_t b1){
    asm volatile("mma.sync.aligned.m16n8k16.row.col.f32.f16.f16.f32 "
        "{%0,%1,%2,%3}, {%4,%5,%6,%7}, {%8,%9}, {%0,%1,%2,%3};"
        : "+f"(c[0]), "+f"(c[1]), "+f"(c[2]), "+f"(c[3])
        : "r"(a[0]), "r"(a[1]), "r"(a[2]), "r"(a[3]), "r"(b0), "r"(b1));
}

// ---------------- fp16 conversion for weights -----------------------------
__global__ void conv_w_kernel(const float* __restrict__ src){
    int i = blockIdx.x*256 + threadIdx.x;
    g_w_h[i] = __float2half(src[i]);
}

// ---------------- zero context (accumulated via atomics) -----------------
__global__ void zero_kernel(){
    int i = blockIdx.x*blockDim.x + threadIdx.x;
    if (i < B*E) g_context[i] = 0.f;
}

// ---------------- ws_app[b,n] = h0[b]·ws_w[n] + ws_b[n] + wh_b[n] --------
__global__ void wsapp_kernel(const float* __restrict__ h0,
                             const float* __restrict__ ws_w,
                             const float* __restrict__ ws_b,
                             const float* __restrict__ wh_b){
    int b = blockIdx.x;
    int warp = threadIdx.x >> 5, lane = threadIdx.x & 31;
    int n = blockIdx.y * 8 + warp;
    const float* wrow = ws_w + (size_t)n*H;
    const float* hrow = h0 + b*H;
    float acc = 0.f;
    for (int k = lane; k < H; k += 32) acc += hrow[k]*wrow[k];
    #pragma unroll
    for (int o = 16; o > 0; o >>= 1) acc += __shfl_xor_sync(0xffffffffu, acc, o);
    if (lane == 0) g_ws_app[b*H + n] = acc + ws_b[n] + wh_b[n];
}

// ---------------- embedding lookup ---------------------------------------
__global__ void embed_kernel(const int* __restrict__ dec_input,
                             const float* __restrict__ table){
    int b = blockIdx.x, t = threadIdx.x;
    g_embed[b*EMBD + t] = table[(size_t)dec_input[b]*EMBD + t];
}

// ---------------- asymmetric fp16 2-product energy GEMM ------------------
// A (enc) fp32 global -> fp16 hi/lo split in-register -> st.shared.
// B (w) single fp16. energy[m] += sum_n tanh((Ahi+Alo)·B + ws)·v
#define MT 128
#define NTILE 128
#define KC 32
#define NCH (E/KC)                 // 32
#define ROWB 80                    // padded row stride bytes (40 halves)
#define ARRB (128*ROWB)            // 10240 per tile array
#define STG_BYTES (3*ARRB)         // Ahi, Alo, B per stage (30720)
#define WS_OFF (2*STG_BYTES)       // 61440
#define V_OFF  (WS_OFF + 512)
#define EN_SMEM (V_OFF + 512)      // 62464

__global__ __launch_bounds__(256, 2) void energy_mma(
        const float* __restrict__ enc, const float* __restrict__ attn_v){
    extern __shared__ char sm[];
    const int tid  = threadIdx.x;
    const int lane = tid & 31, wid = tid >> 5;
    const int wm = wid & 3;           // 4 M-groups of 32 rows
    const int wn = wid >> 2;          // 2 N-groups of 64 cols
    const int n0 = blockIdx.x * NTILE;
    const int m0 = blockIdx.y * MT;
    const int b  = m0 >> 11;

    float* wsP = (float*)(sm + WS_OFF);
    float* vP  = (float*)(sm + V_OFF);
    for (int j = tid; j < NTILE; j += 256){
        wsP[j] = g_ws_app[b*H + n0 + j];
        vP[j]  = attn_v[n0 + j];
    }

    const uint32_t smb = smem_u32(sm);
    const __half* Bg = g_w_h + (size_t)n0*E;

    // per-thread A mapping: row r, k-half kh (16 floats)
    const int ar = tid >> 1;
    const int kh = tid & 1;
    const float* Abase = enc + (size_t)(m0 + ar)*E + kh*16;

    auto loadB = [&](int stage, int k0){
        uint32_t stg = smb + (stage&1)*STG_BYTES + 2*ARRB;
        #pragma unroll
        for (int it = 0; it < 2; it++){
            int f = tid + it*256;          // 0..511
            int r = f >> 2, j = f & 3;
            cp16(stg + r*ROWB + j*16, Bg + (size_t)r*E + k0 + j*8);
        }
        cp_commit();
    };

    float areg[16];
    auto loadA = [&](int k0){
        const float4* gp = (const float4*)(Abase + k0);
        #pragma unroll
        for (int q = 0; q < 4; q++){
            float4 v = gp[q];
            areg[q*4+0] = v.x; areg[q*4+1] = v.y; areg[q*4+2] = v.z; areg[q*4+3] = v.w;
        }
    };
    auto storeA = [&](int stage){
        uint32_t off0 = (stage&1)*STG_BYTES;
        __half hb[16], lb[16];
        #pragma unroll
        for (int q = 0; q < 16; q++){
            hb[q] = __float2half(areg[q]);
            lb[q] = __float2half(areg[q] - __half2float(hb[q]));
        }
        uint32_t off = off0 + (uint32_t)ar*ROWB + kh*32;
        *(uint4*)(sm + off)              = *(uint4*)&hb[0];
        *(uint4*)(sm + off + 16)         = *(uint4*)&hb[8];
        *(uint4*)(sm + ARRB + off)       = *(uint4*)&lb[0];
        *(uint4*)(sm + ARRB + off + 16)  = *(uint4*)&lb[8];
    };

    float c[2][8][4];
    #pragma unroll
    for (int t = 0; t < 2; t++)
        #pragma unroll
        for (int j = 0; j < 8; j++)
            #pragma unroll
            for (int q = 0; q < 4; q++) c[t][j][q] = 0.f;

    // prologue: B(0) in flight; A(0) stored to slot 0; A(1) in regs
    loadB(0, 0);
    loadA(0);
    storeA(0);
    loadA(KC);

    for (int i = 0; i < NCH; i++){
        cp_wait0();              // B(i) arrived
        __syncthreads();         // B(i)+A(i) stores visible; MMA(i-1) retired
        if (i + 1 < NCH){
            loadB(i+1, (i+1)*KC);
            storeA(i+1);
            if (i + 2 < NCH) loadA((i+2)*KC);
        }

        const uint32_t stg = smb + (i&1)*STG_BYTES;
        const uint32_t A0 = stg, A1 = stg + ARRB, B0 = stg + 2*ARRB;

        #pragma unroll
        for (int kk = 0; kk < 2; kk++){
            uint32_t ah[2][4], al[2][4];
            #pragma unroll
            for (int t = 0; t < 2; t++){
                int row = wm*32 + t*16 + (lane & 15);
                uint32_t off = (uint32_t)row*ROWB + (lane >> 4)*16 + kk*32;
                ldsm4(ah[t], A0 + off);
                ldsm4(al[t], A1 + off);
            }
            #pragma unroll
            for (int p = 0; p < 4; p++){
                int row = wn*64 + p*16 + ((lane >> 4) & 1)*8 + (lane & 7);
                uint32_t off = (uint32_t)row*ROWB + ((lane >> 3) & 1)*16 + kk*32;
                uint32_t rh[4];
                ldsm4(rh, B0 + off);
                #pragma unroll
                for (int t = 0; t < 2; t++){
                    mma_f16(c[t][2*p],   ah[t], rh[0], rh[1]);
                    mma_f16(c[t][2*p],   al[t], rh[0], rh[1]);
                    mma_f16(c[t][2*p+1], ah[t], rh[2], rh[3]);
                    mma_f16(c[t][2*p+1], al[t], rh[2], rh[3]);
                }
            }
        }
    }

    // epilogue: tanh + dot attn_v, reduce 4-lane groups, write partials
    float p4[4] = {0.f, 0.f, 0.f, 0.f};
    #pragma unroll
    for (int t = 0; t < 2; t++)
        #pragma unroll
        for (int j = 0; j < 8; j++)
            #pragma unroll
            for (int q = 0; q < 4; q++){
                int nloc = wn*64 + j*8 + (lane & 3)*2 + (q & 1);
                float x = c[t][j][q] + wsP[nloc];
                p4[t*2 + (q >> 1)] += tanhf(x) * vP[nloc];
            }
    #pragma unroll
    for (int q = 0; q < 4; q++){
        p4[q] += __shfl_xor_sync(0xffffffffu, p4[q], 1);
        p4[q] += __shfl_xor_sync(0xffffffffu, p4[q], 2);
    }
    __syncthreads();
    float* red = (float*)(sm);                    // reuse stage smem
    if ((lane & 3) == 0){
        int rloc = wm*32 + (lane >> 2);
        if (wn == 0){
            red[rloc]      = p4[0];
            red[rloc + 8]  = p4[1];
            red[rloc + 16] = p4[2];
            red[rloc + 24] = p4[3];
        }
    }
    __syncthreads();
    if (wn == 1 && (lane & 3) == 0){
        int rloc = wm*32 + (lane >> 2);
        g_energy4[blockIdx.x][m0 + rloc]      = red[rloc]      + p4[0];
        g_energy4[blockIdx.x][m0 + rloc + 8]  = red[rloc + 8]  + p4[1];
        g_energy4[blockIdx.x][m0 + rloc + 16] = red[rloc + 16] + p4[2];
        g_energy4[blockIdx.x][m0 + rloc + 24] = red[rloc + 24] + p4[3];
    }
}

// ---------------- softmax over S per batch (combines 4 partials) ---------
__global__ void attn_softmax(){
    const int b = blockIdx.x, t = threadIdx.x;   // 256 threads, 8 elems/thread
    __shared__ float red[8];
    float ev[8];
    float m = -1e30f;
    #pragma unroll
    for (int q = 0; q < 8; q++){
        int idx = b*S + q*256 + t;
        float v = g_energy4[0][idx] + g_energy4[1][idx] + g_energy4[2][idx] + g_energy4[3][idx];
        ev[q] = v;
        m = fmaxf(m, v);
    }
    #pragma unroll
    for (int o = 16; o > 0; o >>= 1) m = fmaxf(m, __shfl_xor_sync(0xffffffffu, m, o));
    if ((t & 31) == 0) red[t >> 5] = m;
    __syncthreads();
    if (t == 0){ float mm = red[0]; for (int i = 1; i < 8; i++) mm = fmaxf(mm, red[i]); red[0] = mm; }
    __syncthreads();
    m = red[0];
    __syncthreads();
    float s = 0.f;
    #pragma unroll
    for (int q = 0; q < 8; q++){ ev[q] = __expf(ev[q]-m); s += ev[q]; }
    #pragma unroll
    for (int o = 16; o > 0; o >>= 1) s += __shfl_xor_sync(0xffffffffu, s, o);
    if ((t & 31) == 0) red[t >> 5] = s;
    __syncthreads();
    if (t == 0){ float ss = 0.f; for (int i = 0; i < 8; i++) ss += red[i]; red[0] = ss; }
    __syncthreads();
    float inv = 1.f / red[0];
    #pragma unroll
    for (int q = 0; q < 8; q++) g_attn[b*S + q*256 + t] = ev[q] * inv;
}

// ---------------- context[b,e] = sum_s attn[b,s]*enc[b,s,e] --------------
__global__ void context_kernel(const float* __restrict__ enc){
    const int b = blockIdx.x, ec = blockIdx.y, sc = blockIdx.z;
    __shared__ float a_s[512];
    const int t = threadIdx.x;
    for (int i = t; i < 512; i += 256) a_s[i] = g_attn[b*S + sc*512 + i];
    __syncthreads();
    const int e = ec*256 + t;
    const float* base = enc + ((size_t)b*S + sc*512)*E + e;
    float acc = 0.f;
    #pragma unroll 4
    for (int s = 0; s < 512; s++) acc = fmaf(a_s[s], base[(size_t)s*E], acc);
    atomicAdd(&g_context[b*E + e], acc);
}

// ---------------- LSTM gates GEMM ----------------------------------------
__global__ __launch_bounds__(256) void gates_gemm(
        const float* __restrict__ h0,
        const float* __restrict__ w_ih,
        const float* __restrict__ w_hh,
        const float* __restrict__ b_ih,
        const float* __restrict__ b_hh){
    __shared__ float Xs[16][65];
    __shared__ float Ws[16][65];
    const int n0 = blockIdx.x * 64;
    const int tid = threadIdx.x;
    const int tx = tid & 15, ty = tid >> 4;
    float acc[4][4];
    #pragma unroll
    for (int i = 0; i < 4; i++)
        #pragma unroll
        for (int j = 0; j < 4; j++) acc[i][j] = 0.f;

    for (int k0 = 0; k0 < 1792; k0 += 16) {
        for (int i = tid; i < 64*16; i += 256){
            int m = i >> 4, kk = i & 15, k = k0 + kk;
            float xv;
            if (k < E)            xv = g_context[m*E + k];
            else if (k < E+EMBD)  xv = g_embed[m*EMBD + (k - E)];
            else                  xv = h0[m*H + (k - E - EMBD)];
            Xs[kk][m] = xv;
        }
        for (int i = tid; i < 64*16; i += 256){
            int nn = i >> 4, kk = i & 15, k = k0 + kk, n = n0 + nn;
            float wv = (k < E+EMBD) ? w_ih[(size_t)n*(E+EMBD) + k]
                                    : w_hh[(size_t)n*H + (k - E - EMBD)];
            Ws[kk][nn] = wv;
        }
        __syncthreads();
        #pragma unroll
        for (int kk = 0; kk < 16; kk++){
            float ra[4], rb[4];
            #pragma unroll
            for (int i = 0; i < 4; i++) ra[i] = Xs[kk][ty*4+i];
            #pragma unroll
            for (int j = 0; j < 4; j++) rb[j] = Ws[kk][tx*4+j];
            #pragma unroll
            for (int i = 0; i < 4; i++)
                #pragma unroll
                for (int j = 0; j < 4; j++) acc[i][j] = fmaf(ra[i], rb[j], acc[i][j]);
        }
        __syncthreads();
    }
    #pragma unroll
    for (int i = 0; i < 4; i++)
        #pragma unroll
        for (int j = 0; j < 4; j++){
            int m = ty*4+i, n = n0 + tx*4+j;
            g_gates[m*(4*H) + n] = acc[i][j] + b_ih[n] + b_hh[n];
        }
}

// ---------------- LSTM pointwise -----------------------------------------
__global__ void lstm_kernel(const float* __restrict__ c0, float* __restrict__ out){
    const int b = blockIdx.x, h = threadIdx.x;
    const float* g = g_gates + b*(4*H);
    float ig = sigf(g[h]);
    float fg = sigf(g[H + h]);
    float gg = tanhf(g[2*H + h]);
    float og = sigf(g[3*H + h]);
    float c  = fg * c0[b*H + h] + ig * gg;
    float ht = og * tanhf(c);
    out[OUT_HT + b*H + h] = ht;
    out[OUT_CT + b*H + h] = c;
}

// ---------------- logits = h_t @ v_w.T + v_b -----------------------------
__global__ __launch_bounds__(256) void logits_gemm(
        const float* __restrict__ ht,
        const float* __restrict__ v_w,
        const float* __restrict__ v_b){
    __shared__ float Hs[32][64];
    __shared__ float Vs[32][128];
    const int v0 = blockIdx.x * 128;
    const int tid = threadIdx.x;
    const int tx = tid & 15, ty = tid >> 4;
    float acc[4][8];
    #pragma unroll
    for (int i = 0; i < 4; i++)
        #pragma unroll
        for (int j = 0; j < 8; j++) acc[i][j] = 0.f;

    for (int k0 = 0; k0 < H; k0 += 32) {
        for (int fl = tid; fl < 512; fl += 256){
            int m = fl >> 3, kq = (fl & 7) << 2;
            float4 hv = *(const float4*)(ht + (size_t)m*H + k0 + kq);
            Hs[kq+0][m]=hv.x; Hs[kq+1][m]=hv.y; Hs[kq+2][m]=hv.z; Hs[kq+3][m]=hv.w;
        }
        for (int fl = tid; fl < 1024; fl += 256){
            int vr = fl >> 3, kq = (fl & 7) << 2;
            int v = v0 + vr;
            float4 wv = make_float4(0.f,0.f,0.f,0.f);
            if (v < V) wv = *(const float4*)(v_w + (size_t)v*H + k0 + kq);
            Vs[kq+0][vr]=wv.x; Vs[kq+1][vr]=wv.y; Vs[kq+2][vr]=wv.z; Vs[kq+3][vr]=wv.w;
        }
        __syncthreads();
        #pragma unroll
        for (int kk = 0; kk < 32; kk++){
            float4 a0 = *(const float4*)(&Hs[kk][ty*4]);
            float4 b0 = *(const float4*)(&Vs[kk][tx*8]);
            float4 b1 = *(const float4*)(&Vs[kk][tx*8+4]);
            float ra[4] = {a0.x,a0.y,a0.z,a0.w};
            float rb[8] = {b0.x,b0.y,b0.z,b0.w,b1.x,b1.y,b1.z,b1.w};
            #pragma unroll
            for (int i = 0; i < 4; i++)
                #pragma unroll
                for (int j = 0; j < 8; j++) acc[i][j] = fmaf(ra[i], rb[j], acc[i][j]);
        }
        __syncthreads();
    }
    #pragma unroll
    for (int i = 0; i < 4; i++)
        #pragma unroll
        for (int j = 0; j < 8; j++){
            int m = ty*4+i, v = v0 + tx*8+j;
            if (v < V) g_logits[(size_t)m*V + v] = acc[i][j] + v_b[v];
        }
}

// ---------------- p_gen ---------------------------------------------------
__global__ void pgen_kernel(const float* __restrict__ ht,
                            const float* __restrict__ wh_vec,
                            const float* __restrict__ ws_vec,
                            const float* __restrict__ wx_vec){
    const int b = blockIdx.x, t = threadIdx.x;
    __shared__ float red[8];
    float acc = 0.f;
    for (int i = t; i < E;    i += 256) acc += g_context[b*E + i]   * wh_vec[i];
    for (int i = t; i < H;    i += 256) acc += ht[b*H + i]          * ws_vec[i];
    for (int i = t; i < EMBD; i += 256) acc += g_embed[b*EMBD + i]  * wx_vec[i];
    #pragma unroll
    for (int o = 16; o > 0; o >>= 1) acc += __shfl_xor_sync(0xffffffffu, acc, o);
    if ((t & 31) == 0) red[t >> 5] = acc;
    __syncthreads();
    if (t == 0){
        float s = 0.f;
        for (int i = 0; i < 8; i++) s += red[i];
        g_pgen[b] = sigf(s);
    }
}

// ---------------- vocab softmax * p_gen -> out ---------------------------
__global__ void vocab_out_kernel(float* __restrict__ out){
    const int b = blockIdx.x, t = threadIdx.x;
    __shared__ float red[16];
    const float* row = g_logits + (size_t)b*V;
    float m = -1e30f;
    for (int v = t; v < V; v += 512) m = fmaxf(m, row[v]);
    #pragma unroll
    for (int o = 16; o > 0; o >>= 1) m = fmaxf(m, __shfl_xor_sync(0xffffffffu, m, o));
    if ((t & 31) == 0) red[t >> 5] = m;
    __syncthreads();
    if (t == 0){ float mm = red[0]; for (int i = 1; i < 16; i++) mm = fmaxf(mm, red[i]); red[0] = mm; }
    __syncthreads();
    m = red[0];
    __syncthreads();
    float s = 0.f;
    for (int v = t; v < V; v += 512) s += __expf(row[v]-m);
    #pragma unroll
    for (int o = 16; o > 0; o >>= 1) s += __shfl_xor_sync(0xffffffffu, s, o);
    if ((t & 31) == 0) red[t >> 5] = s;
    __syncthreads();
    if (t == 0){ float ss = 0.f; for (int i = 0; i < 16; i++) ss += red[i]; red[0] = ss; }
    __syncthreads();
    const float scale = g_pgen[b] / red[0];
    for (int v = t; v < V; v += 512) out[(size_t)b*V + v] = __expf(row[v]-m) * scale;
}

// ---------------- copy-mechanism scatter ---------------------------------
__global__ void scatter_kernel(const int* __restrict__ enc_inputs,
                               float* __restrict__ out){
    const int idx = blockIdx.x*256 + threadIdx.x;
    if (idx >= MTOT) return;
    const int b = idx >> 11;
    const int tok = enc_inputs[idx];
    atomicAdd(&out[(size_t)b*V + tok], (1.f - g_pgen[b]) * g_attn[idx]);
}

// ---------------- launch --------------------------------------------------
extern "C" void kernel_launch(void* const* d_in, const int* in_sizes, int n_in,
                              void* d_out, int out_size) {
    const float* enc_out   = (const float*)d_in[0];
    const float* h0        = (const float*)d_in[1];
    const float* c0        = (const float*)d_in[2];
    const int*   dec_input = (const int*)  d_in[3];
    const int*   enc_inputs= (const int*)  d_in[4];
    const float* embed_tab = (const float*)d_in[5];
    const float* attn_wh_w = (const float*)d_in[6];
    const float* attn_wh_b = (const float*)d_in[7];
    const float* attn_ws_w = (const float*)d_in[8];
    const float* attn_ws_b = (const float*)d_in[9];
    const float* attn_v    = (const float*)d_in[10];
    const float* lstm_w_ih = (const float*)d_in[11];
    const float* lstm_w_hh = (const float*)d_in[12];
    const float* lstm_b_ih = (const float*)d_in[13];
    const float* lstm_b_hh = (const float*)d_in[14];
    const float* wh_vec    = (const float*)d_in[15];
    const float* ws_vec    = (const float*)d_in[16];
    const float* wx_vec    = (const float*)d_in[17];
    const float* v_w       = (const float*)d_in[18];
    const float* v_b       = (const float*)d_in[19];
    float* out = (float*)d_out;
    const float* ht = out + OUT_HT;

    static bool attr_set = false;
    if (!attr_set){
        cudaFuncSetAttribute(energy_mma, cudaFuncAttributeMaxDynamicSharedMemorySize, EN_SMEM);
        attr_set = true;
    }

    // energy_mma is the 4th launch (ncu capture slot)
    conv_w_kernel<<<2048, 256>>>(attn_wh_w);
    wsapp_kernel<<<dim3(B, 64), 256>>>(h0, attn_ws_w, attn_ws_b, attn_wh_b);
    zero_kernel<<<256, 256>>>();
    energy_mma<<<dim3(H/NTILE, MTOT/MT), 256, EN_SMEM>>>(enc_out, attn_v);
    embed_kernel<<<B, 256>>>(dec_input, embed_tab);
    attn_softmax<<<B, 256>>>();
    context_kernel<<<dim3(B, 4, 4), 256>>>(enc_out);
    gates_gemm<<<(4*H)/64, 256>>>(h0, lstm_w_ih, lstm_w_hh, lstm_b_ih, lstm_b_hh);
    lstm_kernel<<<B, 512>>>(c0, out);
    logits_gemm<<<(V + 127)/128, 256>>>(ht, v_w, v_b);
    pgen_kernel<<<B, 256>>>(ht, wh_vec, ws_vec, wx_vec);
    vocab_out_kernel<<<B, 512>>>(out);
    scatter_kernel<<<(MTOT + 255)/256, 256>>>(enc_inputs, out);
}

// round 12
// speedup vs baseline: 3.0920x; 1.0610x over previous
#include <cuda_runtime.h>
#include <cuda_fp16.h>
#include <math.h>
#include <stdint.h>

#define B 64
#define S 2048
#define E 1024
#define H 512
#define EMBD 256
#define V 50257
#define MTOT (B*S)

#define OUT_HT ((size_t)B*V)
#define OUT_CT (OUT_HT + (size_t)B*H)

// ---------------- device scratch (no allocations allowed) ----------------
__device__ float g_ws_app[B*H];        // h0@ws_w.T + ws_b + wh_b
__device__ float g_energy4[4][MTOT];   // per-n-block energy partials
__device__ float g_attn[MTOT];
__device__ float g_context[B*E];
__device__ float g_embed[B*EMBD];
__device__ float g_gates[B*4*H];
__device__ float g_logits[(size_t)B*V];
__device__ float g_pgen[B];

__device__ __half g_w_h[H*E];          // attn_wh_w fp16
__device__ __half g_vw_h[(size_t)V*H]; // v_w fp16
__device__ __half g_ht_hi[B*H];        // h_t fp16 hi
__device__ __half g_ht_lo[B*H];        // h_t fp16 lo

__device__ __forceinline__ float sigf(float x){ return 1.f/(1.f+__expf(-x)); }

// ======================= portable PTX helpers =============================
__device__ __forceinline__ uint32_t smem_u32(const void* p){
    uint32_t a;
    asm("{ .reg .u64 t; cvta.to.shared.u64 t, %1; cvt.u32.u64 %0, t; }" : "=r"(a) : "l"(p));
    return a;
}
__device__ __forceinline__ void cp16(uint32_t dst, const void* src){
    asm volatile("cp.async.cg.shared.global [%0], [%1], 16;" :: "r"(dst), "l"(src));
}
__device__ __forceinline__ void cp_commit(){ asm volatile("cp.async.commit_group;" ::: "memory"); }
__device__ __forceinline__ void cp_wait0(){ asm volatile("cp.async.wait_group 0;" ::: "memory"); }

__device__ __forceinline__ void ldsm4(uint32_t* r, uint32_t addr){
    asm volatile("ldmatrix.sync.aligned.m8n8.x4.shared.b16 {%0,%1,%2,%3}, [%4];"
        : "=r"(r[0]), "=r"(r[1]), "=r"(r[2]), "=r"(r[3]) : "r"(addr));
}
__device__ __forceinline__ void mma_f16(float* c, const uint32_t* a, uint32_t b0, uint32_t b1){
    asm volatile("mma.sync.aligned.m16n8k16.row.col.f32.f16.f16.f32 "
        "{%0,%1,%2,%3}, {%4,%5,%6,%7}, {%8,%9}, {%0,%1,%2,%3};"
        : "+f"(c[0]), "+f"(c[1]), "+f"(c[2]), "+f"(c[3])
        : "r"(a[0]), "r"(a[1]), "r"(a[2]), "r"(a[3]), "r"(b0), "r"(b1));
}

// ---------------- fp16 conversion kernels ---------------------------------
__global__ void conv_w_kernel(const float* __restrict__ src){
    int i = blockIdx.x*256 + threadIdx.x;
    g_w_h[i] = __float2half(src[i]);
}
__global__ void conv_vw_kernel(const float* __restrict__ src){
    size_t i = (size_t)blockIdx.x*256 + threadIdx.x;   // V*H = 256*100514 exactly
    g_vw_h[i] = __float2half(src[i]);
}

// ---------------- zero context (accumulated via atomics) -----------------
__global__ void zero_kernel(){
    int i = blockIdx.x*blockDim.x + threadIdx.x;
    if (i < B*E) g_context[i] = 0.f;
}

// ---------------- ws_app[b,n] = h0[b]·ws_w[n] + ws_b[n] + wh_b[n] --------
__global__ void wsapp_kernel(const float* __restrict__ h0,
                             const float* __restrict__ ws_w,
                             const float* __restrict__ ws_b,
                             const float* __restrict__ wh_b){
    int b = blockIdx.x;
    int warp = threadIdx.x >> 5, lane = threadIdx.x & 31;
    int n = blockIdx.y * 8 + warp;
    const float* wrow = ws_w + (size_t)n*H;
    const float* hrow = h0 + b*H;
    float acc = 0.f;
    for (int k = lane; k < H; k += 32) acc += hrow[k]*wrow[k];
    #pragma unroll
    for (int o = 16; o > 0; o >>= 1) acc += __shfl_xor_sync(0xffffffffu, acc, o);
    if (lane == 0) g_ws_app[b*H + n] = acc + ws_b[n] + wh_b[n];
}

// ---------------- embedding lookup ---------------------------------------
__global__ void embed_kernel(const int* __restrict__ dec_input,
                             const float* __restrict__ table){
    int b = blockIdx.x, t = threadIdx.x;
    g_embed[b*EMBD + t] = table[(size_t)dec_input[b]*EMBD + t];
}

// ---------------- asymmetric fp16 2-product energy GEMM ------------------
#define MT 128
#define NTILE 128
#define KC 32
#define NCH (E/KC)                 // 32
#define ROWB 80
#define ARRB (128*ROWB)            // 10240
#define STG_BYTES (3*ARRB)         // Ahi, Alo, B per stage
#define WS_OFF (2*STG_BYTES)
#define V_OFF  (WS_OFF + 512)
#define EN_SMEM (V_OFF + 512)

__global__ __launch_bounds__(256, 2) void energy_mma(
        const float* __restrict__ enc, const float* __restrict__ attn_v){
    extern __shared__ char sm[];
    const int tid  = threadIdx.x;
    const int lane = tid & 31, wid = tid >> 5;
    const int wm = wid & 3;
    const int wn = wid >> 2;
    const int n0 = blockIdx.x * NTILE;
    const int m0 = blockIdx.y * MT;
    const int b  = m0 >> 11;

    float* wsP = (float*)(sm + WS_OFF);
    float* vP  = (float*)(sm + V_OFF);
    for (int j = tid; j < NTILE; j += 256){
        wsP[j] = g_ws_app[b*H + n0 + j];
        vP[j]  = attn_v[n0 + j];
    }

    const uint32_t smb = smem_u32(sm);
    const __half* Bg = g_w_h + (size_t)n0*E;

    const int ar = tid >> 1;
    const int kh = tid & 1;
    const float* Abase = enc + (size_t)(m0 + ar)*E + kh*16;

    auto loadB = [&](int stage, int k0){
        uint32_t stg = smb + (stage&1)*STG_BYTES + 2*ARRB;
        #pragma unroll
        for (int it = 0; it < 2; it++){
            int f = tid + it*256;
            int r = f >> 2, j = f & 3;
            cp16(stg + r*ROWB + j*16, Bg + (size_t)r*E + k0 + j*8);
        }
        cp_commit();
    };

    float areg[16];
    auto loadA = [&](int k0){
        const float4* gp = (const float4*)(Abase + k0);
        #pragma unroll
        for (int q = 0; q < 4; q++){
            float4 v = gp[q];
            areg[q*4+0] = v.x; areg[q*4+1] = v.y; areg[q*4+2] = v.z; areg[q*4+3] = v.w;
        }
    };
    auto storeA = [&](int stage){
        uint32_t off0 = (stage&1)*STG_BYTES;
        __half hb[16], lb[16];
        #pragma unroll
        for (int q = 0; q < 16; q++){
            hb[q] = __float2half(areg[q]);
            lb[q] = __float2half(areg[q] - __half2float(hb[q]));
        }
        uint32_t off = off0 + (uint32_t)ar*ROWB + kh*32;
        *(uint4*)(sm + off)              = *(uint4*)&hb[0];
        *(uint4*)(sm + off + 16)         = *(uint4*)&hb[8];
        *(uint4*)(sm + ARRB + off)       = *(uint4*)&lb[0];
        *(uint4*)(sm + ARRB + off + 16)  = *(uint4*)&lb[8];
    };

    float c[2][8][4];
    #pragma unroll
    for (int t = 0; t < 2; t++)
        #pragma unroll
        for (int j = 0; j < 8; j++)
            #pragma unroll
            for (int q = 0; q < 4; q++) c[t][j][q] = 0.f;

    loadB(0, 0);
    loadA(0);
    storeA(0);
    loadA(KC);

    for (int i = 0; i < NCH; i++){
        cp_wait0();
        __syncthreads();
        if (i + 1 < NCH){
            loadB(i+1, (i+1)*KC);
            storeA(i+1);
            if (i + 2 < NCH) loadA((i+2)*KC);
        }

        const uint32_t stg = smb + (i&1)*STG_BYTES;
        const uint32_t A0 = stg, A1 = stg + ARRB, B0 = stg + 2*ARRB;

        #pragma unroll
        for (int kk = 0; kk < 2; kk++){
            uint32_t ah[2][4], al[2][4];
            #pragma unroll
            for (int t = 0; t < 2; t++){
                int row = wm*32 + t*16 + (lane & 15);
                uint32_t off = (uint32_t)row*ROWB + (lane >> 4)*16 + kk*32;
                ldsm4(ah[t], A0 + off);
                ldsm4(al[t], A1 + off);
            }
            #pragma unroll
            for (int p = 0; p < 4; p++){
                int row = wn*64 + p*16 + ((lane >> 4) & 1)*8 + (lane & 7);
                uint32_t off = (uint32_t)row*ROWB + ((lane >> 3) & 1)*16 + kk*32;
                uint32_t rh[4];
                ldsm4(rh, B0 + off);
                #pragma unroll
                for (int t = 0; t < 2; t++){
                    mma_f16(c[t][2*p],   ah[t], rh[0], rh[1]);
                    mma_f16(c[t][2*p],   al[t], rh[0], rh[1]);
                    mma_f16(c[t][2*p+1], ah[t], rh[2], rh[3]);
                    mma_f16(c[t][2*p+1], al[t], rh[2], rh[3]);
                }
            }
        }
    }

    float p4[4] = {0.f, 0.f, 0.f, 0.f};
    #pragma unroll
    for (int t = 0; t < 2; t++)
        #pragma unroll
        for (int j = 0; j < 8; j++)
            #pragma unroll
            for (int q = 0; q < 4; q++){
                int nloc = wn*64 + j*8 + (lane & 3)*2 + (q & 1);
                float x = c[t][j][q] + wsP[nloc];
                p4[t*2 + (q >> 1)] += tanhf(x) * vP[nloc];
            }
    #pragma unroll
    for (int q = 0; q < 4; q++){
        p4[q] += __shfl_xor_sync(0xffffffffu, p4[q], 1);
        p4[q] += __shfl_xor_sync(0xffffffffu, p4[q], 2);
    }
    __syncthreads();
    float* red = (float*)(sm);
    if ((lane & 3) == 0){
        int rloc = wm*32 + (lane >> 2);
        if (wn == 0){
            red[rloc]      = p4[0];
            red[rloc + 8]  = p4[1];
            red[rloc + 16] = p4[2];
            red[rloc + 24] = p4[3];
        }
    }
    __syncthreads();
    if (wn == 1 && (lane & 3) == 0){
        int rloc = wm*32 + (lane >> 2);
        g_energy4[blockIdx.x][m0 + rloc]      = red[rloc]      + p4[0];
        g_energy4[blockIdx.x][m0 + rloc + 8]  = red[rloc + 8]  + p4[1];
        g_energy4[blockIdx.x][m0 + rloc + 16] = red[rloc + 16] + p4[2];
        g_energy4[blockIdx.x][m0 + rloc + 24] = red[rloc + 24] + p4[3];
    }
}

// ---------------- softmax over S per batch (combines 4 partials) ---------
__global__ void attn_softmax(){
    const int b = blockIdx.x, t = threadIdx.x;
    __shared__ float red[8];
    float ev[8];
    float m = -1e30f;
    #pragma unroll
    for (int q = 0; q < 8; q++){
        int idx = b*S + q*256 + t;
        float v = g_energy4[0][idx] + g_energy4[1][idx] + g_energy4[2][idx] + g_energy4[3][idx];
        ev[q] = v;
        m = fmaxf(m, v);
    }
    #pragma unroll
    for (int o = 16; o > 0; o >>= 1) m = fmaxf(m, __shfl_xor_sync(0xffffffffu, m, o));
    if ((t & 31) == 0) red[t >> 5] = m;
    __syncthreads();
    if (t == 0){ float mm = red[0]; for (int i = 1; i < 8; i++) mm = fmaxf(mm, red[i]); red[0] = mm; }
    __syncthreads();
    m = red[0];
    __syncthreads();
    float s = 0.f;
    #pragma unroll
    for (int q = 0; q < 8; q++){ ev[q] = __expf(ev[q]-m); s += ev[q]; }
    #pragma unroll
    for (int o = 16; o > 0; o >>= 1) s += __shfl_xor_sync(0xffffffffu, s, o);
    if ((t & 31) == 0) red[t >> 5] = s;
    __syncthreads();
    if (t == 0){ float ss = 0.f; for (int i = 0; i < 8; i++) ss += red[i]; red[0] = ss; }
    __syncthreads();
    float inv = 1.f / red[0];
    #pragma unroll
    for (int q = 0; q < 8; q++) g_attn[b*S + q*256 + t] = ev[q] * inv;
}

// ---------------- context[b,e] = sum_s attn[b,s]*enc[b,s,e] --------------
__global__ void context_kernel(const float* __restrict__ enc){
    const int b = blockIdx.x, ec = blockIdx.y, sc = blockIdx.z;
    __shared__ float a_s[512];
    const int t = threadIdx.x;
    for (int i = t; i < 512; i += 256) a_s[i] = g_attn[b*S + sc*512 + i];
    __syncthreads();
    const int e = ec*256 + t;
    const float* base = enc + ((size_t)b*S + sc*512)*E + e;
    float acc = 0.f;
    #pragma unroll 4
    for (int s = 0; s < 512; s++) acc = fmaf(a_s[s], base[(size_t)s*E], acc);
    atomicAdd(&g_context[b*E + e], acc);
}

// ---------------- LSTM gates GEMM ----------------------------------------
__global__ __launch_bounds__(256) void gates_gemm(
        const float* __restrict__ h0,
        const float* __restrict__ w_ih,
        const float* __restrict__ w_hh,
        const float* __restrict__ b_ih,
        const float* __restrict__ b_hh){
    __shared__ float Xs[16][65];
    __shared__ float Ws[16][65];
    const int n0 = blockIdx.x * 64;
    const int tid = threadIdx.x;
    const int tx = tid & 15, ty = tid >> 4;
    float acc[4][4];
    #pragma unroll
    for (int i = 0; i < 4; i++)
        #pragma unroll
        for (int j = 0; j < 4; j++) acc[i][j] = 0.f;

    for (int k0 = 0; k0 < 1792; k0 += 16) {
        for (int i = tid; i < 64*16; i += 256){
            int m = i >> 4, kk = i & 15, k = k0 + kk;
            float xv;
            if (k < E)            xv = g_context[m*E + k];
            else if (k < E+EMBD)  xv = g_embed[m*EMBD + (k - E)];
            else                  xv = h0[m*H + (k - E - EMBD)];
            Xs[kk][m] = xv;
        }
        for (int i = tid; i < 64*16; i += 256){
            int nn = i >> 4, kk = i & 15, k = k0 + kk, n = n0 + nn;
            float wv = (k < E+EMBD) ? w_ih[(size_t)n*(E+EMBD) + k]
                                    : w_hh[(size_t)n*H + (k - E - EMBD)];
            Ws[kk][nn] = wv;
        }
        __syncthreads();
        #pragma unroll
        for (int kk = 0; kk < 16; kk++){
            float ra[4], rb[4];
            #pragma unroll
            for (int i = 0; i < 4; i++) ra[i] = Xs[kk][ty*4+i];
            #pragma unroll
            for (int j = 0; j < 4; j++) rb[j] = Ws[kk][tx*4+j];
            #pragma unroll
            for (int i = 0; i < 4; i++)
                #pragma unroll
                for (int j = 0; j < 4; j++) acc[i][j] = fmaf(ra[i], rb[j], acc[i][j]);
        }
        __syncthreads();
    }
    #pragma unroll
    for (int i = 0; i < 4; i++)
        #pragma unroll
        for (int j = 0; j < 4; j++){
            int m = ty*4+i, n = n0 + tx*4+j;
            g_gates[m*(4*H) + n] = acc[i][j] + b_ih[n] + b_hh[n];
        }
}

// ---------------- LSTM pointwise (also emits fp16 hi/lo h_t) -------------
__global__ void lstm_kernel(const float* __restrict__ c0, float* __restrict__ out){
    const int b = blockIdx.x, h = threadIdx.x;
    const float* g = g_gates + b*(4*H);
    float ig = sigf(g[h]);
    float fg = sigf(g[H + h]);
    float gg = tanhf(g[2*H + h]);
    float og = sigf(g[3*H + h]);
    float c  = fg * c0[b*H + h] + ig * gg;
    float ht = og * tanhf(c);
    out[OUT_HT + b*H + h] = ht;
    out[OUT_CT + b*H + h] = c;
    __half hh = __float2half(ht);
    g_ht_hi[b*H + h] = hh;
    g_ht_lo[b*H + h] = __float2half(ht - __half2float(hh));
}

// ---------------- logits via fp16 2-product HMMA -------------------------
// logits[64, V] = (Hhi+Hlo)[64,512] @ v_w_h.T[512,V] + v_b
#define LKC 32
#define LCH (H/LKC)                // 16
#define LRB 80
#define LH_ARR (64*LRB)            // 5120
#define LW_ARR (128*LRB)           // 10240
#define LSTG (2*LH_ARR + LW_ARR)   // 20480

__global__ __launch_bounds__(256) void logits_mma(const float* __restrict__ vb){
    __shared__ char sm2[2*LSTG];
    const int tid  = threadIdx.x;
    const int lane = tid & 31, wid = tid >> 5;
    const int wm = wid & 3;            // 4 M-groups of 16 rows (M=64)
    const int wn = wid >> 2;           // 2 N-groups of 64 cols
    const int n0 = blockIdx.x * 128;
    const uint32_t smb = smem_u32(sm2);

    auto loadAB = [&](int i){
        uint32_t stg = smb + (i&1)*LSTG;
        int k0 = i*LKC;
        #pragma unroll
        for (int it = 0; it < 4; it++){
            int f = tid + it*256;              // 0..1023
            if (f < 512){                       // H hi/lo: 2 x 64 rows x 4 chunks
                int digit = f >> 8, idx = f & 255;
                int r = idx >> 2, j = idx & 3;
                const __half* src = (digit ? g_ht_lo : g_ht_hi) + r*H + k0 + j*8;
                cp16(stg + digit*LH_ARR + r*LRB + j*16, src);
            } else {                            // W: 128 rows x 4 chunks
                int idx = f - 512;
                int r = idx >> 2, j = idx & 3;
                int rg = n0 + r; if (rg >= V) rg = V - 1;
                cp16(stg + 2*LH_ARR + r*LRB + j*16,
                     g_vw_h + (size_t)rg*H + k0 + j*8);
            }
        }
        cp_commit();
    };

    float c[8][4];
    #pragma unroll
    for (int j = 0; j < 8; j++)
        #pragma unroll
        for (int q = 0; q < 4; q++) c[j][q] = 0.f;

    loadAB(0);

    for (int i = 0; i < LCH; i++){
        cp_wait0();
        __syncthreads();
        if (i + 1 < LCH) loadAB(i+1);

        const uint32_t stg = smb + (i&1)*LSTG;
        const uint32_t A0 = stg, A1 = stg + LH_ARR, B0 = stg + 2*LH_ARR;

        #pragma unroll
        for (int kk = 0; kk < 2; kk++){
            uint32_t ah[4], al[4];
            {
                int row = wm*16 + (lane & 15);
                uint32_t off = (uint32_t)row*LRB + (lane >> 4)*16 + kk*32;
                ldsm4(ah, A0 + off);
                ldsm4(al, A1 + off);
            }
            #pragma unroll
            for (int p = 0; p < 4; p++){
                int row = wn*64 + p*16 + ((lane >> 4) & 1)*8 + (lane & 7);
                uint32_t off = (uint32_t)row*LRB + ((lane >> 3) & 1)*16 + kk*32;
                uint32_t rh[4];
                ldsm4(rh, B0 + off);
                mma_f16(c[2*p],   ah, rh[0], rh[1]);
                mma_f16(c[2*p],   al, rh[0], rh[1]);
                mma_f16(c[2*p+1], ah, rh[2], rh[3]);
                mma_f16(c[2*p+1], al, rh[2], rh[3]);
            }
        }
    }

    #pragma unroll
    for (int j = 0; j < 8; j++)
        #pragma unroll
        for (int q = 0; q < 4; q++){
            int m = wm*16 + (lane >> 2) + (q >> 1)*8;
            int v = n0 + wn*64 + j*8 + (lane & 3)*2 + (q & 1);
            if (v < V) g_logits[(size_t)m*V + v] = c[j][q] + vb[v];
        }
}

// ---------------- p_gen ---------------------------------------------------
__global__ void pgen_kernel(const float* __restrict__ ht,
                            const float* __restrict__ wh_vec,
                            const float* __restrict__ ws_vec,
                            const float* __restrict__ wx_vec){
    const int b = blockIdx.x, t = threadIdx.x;
    __shared__ float red[8];
    float acc = 0.f;
    for (int i = t; i < E;    i += 256) acc += g_context[b*E + i]   * wh_vec[i];
    for (int i = t; i < H;    i += 256) acc += ht[b*H + i]          * ws_vec[i];
    for (int i = t; i < EMBD; i += 256) acc += g_embed[b*EMBD + i]  * wx_vec[i];
    #pragma unroll
    for (int o = 16; o > 0; o >>= 1) acc += __shfl_xor_sync(0xffffffffu, acc, o);
    if ((t & 31) == 0) red[t >> 5] = acc;
    __syncthreads();
    if (t == 0){
        float s = 0.f;
        for (int i = 0; i < 8; i++) s += red[i];
        g_pgen[b] = sigf(s);
    }
}

// ---------------- vocab softmax * p_gen -> out ---------------------------
__global__ void vocab_out_kernel(float* __restrict__ out){
    const int b = blockIdx.x, t = threadIdx.x;
    __shared__ float red[16];
    const float* row = g_logits + (size_t)b*V;
    float m = -1e30f;
    for (int v = t; v < V; v += 512) m = fmaxf(m, row[v]);
    #pragma unroll
    for (int o = 16; o > 0; o >>= 1) m = fmaxf(m, __shfl_xor_sync(0xffffffffu, m, o));
    if ((t & 31) == 0) red[t >> 5] = m;
    __syncthreads();
    if (t == 0){ float mm = red[0]; for (int i = 1; i < 16; i++) mm = fmaxf(mm, red[i]); red[0] = mm; }
    __syncthreads();
    m = red[0];
    __syncthreads();
    float s = 0.f;
    for (int v = t; v < V; v += 512) s += __expf(row[v]-m);
    #pragma unroll
    for (int o = 16; o > 0; o >>= 1) s += __shfl_xor_sync(0xffffffffu, s, o);
    if ((t & 31) == 0) red[t >> 5] = s;
    __syncthreads();
    if (t == 0){ float ss = 0.f; for (int i = 0; i < 16; i++) ss += red[i]; red[0] = ss; }
    __syncthreads();
    const float scale = g_pgen[b] / red[0];
    for (int v = t; v < V; v += 512) out[(size_t)b*V + v] = __expf(row[v]-m) * scale;
}

// ---------------- copy-mechanism scatter ---------------------------------
__global__ void scatter_kernel(const int* __restrict__ enc_inputs,
                               float* __restrict__ out){
    const int idx = blockIdx.x*256 + threadIdx.x;
    if (idx >= MTOT) return;
    const int b = idx >> 11;
    const int tok = enc_inputs[idx];
    atomicAdd(&out[(size_t)b*V + tok], (1.f - g_pgen[b]) * g_attn[idx]);
}

// ---------------- launch --------------------------------------------------
extern "C" void kernel_launch(void* const* d_in, const int* in_sizes, int n_in,
                              void* d_out, int out_size) {
    const float* enc_out   = (const float*)d_in[0];
    const float* h0        = (const float*)d_in[1];
    const float* c0        = (const float*)d_in[2];
    const int*   dec_input = (const int*)  d_in[3];
    const int*   enc_inputs= (const int*)  d_in[4];
    const float* embed_tab = (const float*)d_in[5];
    const float* attn_wh_w = (const float*)d_in[6];
    const float* attn_wh_b = (const float*)d_in[7];
    const float* attn_ws_w = (const float*)d_in[8];
    const float* attn_ws_b = (const float*)d_in[9];
    const float* attn_v    = (const float*)d_in[10];
    const float* lstm_w_ih = (const float*)d_in[11];
    const float* lstm_w_hh = (const float*)d_in[12];
    const float* lstm_b_ih = (const float*)d_in[13];
    const float* lstm_b_hh = (const float*)d_in[14];
    const float* wh_vec    = (const float*)d_in[15];
    const float* ws_vec    = (const float*)d_in[16];
    const float* wx_vec    = (const float*)d_in[17];
    const float* v_w       = (const float*)d_in[18];
    const float* v_b       = (const float*)d_in[19];
    float* out = (float*)d_out;
    const float* ht = out + OUT_HT;

    static bool attr_set = false;
    if (!attr_set){
        cudaFuncSetAttribute(energy_mma, cudaFuncAttributeMaxDynamicSharedMemorySize, EN_SMEM);
        attr_set = true;
    }

    // energy_mma kept as the 4th launch (ncu capture slot)
    conv_w_kernel<<<2048, 256>>>(attn_wh_w);
    wsapp_kernel<<<dim3(B, 64), 256>>>(h0, attn_ws_w, attn_ws_b, attn_wh_b);
    conv_vw_kernel<<<100514, 256>>>(v_w);
    energy_mma<<<dim3(H/NTILE, MTOT/MT), 256, EN_SMEM>>>(enc_out, attn_v);
    zero_kernel<<<256, 256>>>();
    embed_kernel<<<B, 256>>>(dec_input, embed_tab);
    attn_softmax<<<B, 256>>>();
    context_kernel<<<dim3(B, 4, 4), 256>>>(enc_out);
    gates_gemm<<<(4*H)/64, 256>>>(h0, lstm_w_ih, lstm_w_hh, lstm_b_ih, lstm_b_hh);
    lstm_kernel<<<B, 512>>>(c0, out);
    logits_mma<<<(V + 127)/128, 256>>>(v_b);
    pgen_kernel<<<B, 256>>>(ht, wh_vec, ws_vec, wx_vec);
    vocab_out_kernel<<<B, 512>>>(out);
    scatter_kernel<<<(MTOT + 255)/256, 256>>>(enc_inputs, out);
}

// round 13
// speedup vs baseline: 3.9819x; 1.2878x over previous
#include <cuda_runtime.h>
#include <cuda_fp16.h>
#include <math.h>
#include <stdint.h>

#define B 64
#define S 2048
#define E 1024
#define H 512
#define EMBD 256
#define V 50257
#define MTOT (B*S)

#define OUT_HT ((size_t)B*V)
#define OUT_CT (OUT_HT + (size_t)B*H)

// ---------------- device scratch (no allocations allowed) ----------------
__device__ float g_ws_app[B*H];        // h0@ws_w.T + ws_b + wh_b
__device__ float g_energy4[4][MTOT];   // per-n-block energy partials
__device__ float g_attn[MTOT];
__device__ float g_context[B*E];
__device__ float g_embed[B*EMBD];
__device__ float g_gates4[4][B*4*H];   // per-K-split gate partials
__device__ float g_logits[(size_t)B*V];
__device__ float g_pgen[B];

__device__ __half g_w_h[H*E];          // attn_wh_w fp16
__device__ __half g_vw_h[(size_t)V*H]; // v_w fp16
__device__ __half g_ht_hi[B*H];        // h_t fp16 hi
__device__ __half g_ht_lo[B*H];        // h_t fp16 lo

__device__ __forceinline__ float sigf(float x){ return 1.f/(1.f+__expf(-x)); }
__device__ __forceinline__ float ftanh(float x){
    x = fminf(fmaxf(x, -15.f), 15.f);
    float e2 = __expf(2.f*x);
    return (e2 - 1.f) / (e2 + 1.f);
}

// ======================= portable PTX helpers =============================
__device__ __forceinline__ uint32_t smem_u32(const void* p){
    uint32_t a;
    asm("{ .reg .u64 t; cvta.to.shared.u64 t, %1; cvt.u32.u64 %0, t; }" : "=r"(a) : "l"(p));
    return a;
}
__device__ __forceinline__ void cp16(uint32_t dst, const void* src){
    asm volatile("cp.async.cg.shared.global [%0], [%1], 16;" :: "r"(dst), "l"(src));
}
__device__ __forceinline__ void cp_commit(){ asm volatile("cp.async.commit_group;" ::: "memory"); }
__device__ __forceinline__ void cp_wait0(){ asm volatile("cp.async.wait_group 0;" ::: "memory"); }

__device__ __forceinline__ void ldsm4(uint32_t* r, uint32_t addr){
    asm volatile("ldmatrix.sync.aligned.m8n8.x4.shared.b16 {%0,%1,%2,%3}, [%4];"
        : "=r"(r[0]), "=r"(r[1]), "=r"(r[2]), "=r"(r[3]) : "r"(addr));
}
__device__ __forceinline__ void mma_f16(float* c, const uint32_t* a, uint32_t b0, uint32_t b1){
    asm volatile("mma.sync.aligned.m16n8k16.row.col.f32.f16.f16.f32 "
        "{%0,%1,%2,%3}, {%4,%5,%6,%7}, {%8,%9}, {%0,%1,%2,%3};"
        : "+f"(c[0]), "+f"(c[1]), "+f"(c[2]), "+f"(c[3])
        : "r"(a[0]), "r"(a[1]), "r"(a[2]), "r"(a[3]), "r"(b0), "r"(b1));
}

// ---------------- fp16 conversion kernels ---------------------------------
__global__ void conv_w_kernel(const float* __restrict__ src){
    int i = blockIdx.x*256 + threadIdx.x;
    g_w_h[i] = __float2half(src[i]);
}
__global__ void conv_vw_kernel(const float* __restrict__ src){
    size_t i8 = ((size_t)blockIdx.x*256 + threadIdx.x)*8;
    if (i8 >= (size_t)V*H) return;
    float4 a = *(const float4*)(src + i8);
    float4 b = *(const float4*)(src + i8 + 4);
    __half h[8];
    h[0]=__float2half(a.x); h[1]=__float2half(a.y);
    h[2]=__float2half(a.z); h[3]=__float2half(a.w);
    h[4]=__float2half(b.x); h[5]=__float2half(b.y);
    h[6]=__float2half(b.z); h[7]=__float2half(b.w);
    *(uint4*)(g_vw_h + i8) = *(uint4*)h;
}

// ---------------- zero context (accumulated via atomics) -----------------
__global__ void zero_kernel(){
    int i = blockIdx.x*blockDim.x + threadIdx.x;
    if (i < B*E) g_context[i] = 0.f;
}

// ---------------- ws_app[b,n] = h0[b]·ws_w[n] + ws_b[n] + wh_b[n] --------
__global__ void wsapp_kernel(const float* __restrict__ h0,
                             const float* __restrict__ ws_w,
                             const float* __restrict__ ws_b,
                             const float* __restrict__ wh_b){
    int b = blockIdx.x;
    int warp = threadIdx.x >> 5, lane = threadIdx.x & 31;
    int n = blockIdx.y * 8 + warp;
    const float* wrow = ws_w + (size_t)n*H;
    const float* hrow = h0 + b*H;
    float acc = 0.f;
    for (int k = lane; k < H; k += 32) acc += hrow[k]*wrow[k];
    #pragma unroll
    for (int o = 16; o > 0; o >>= 1) acc += __shfl_xor_sync(0xffffffffu, acc, o);
    if (lane == 0) g_ws_app[b*H + n] = acc + ws_b[n] + wh_b[n];
}

// ---------------- embedding lookup ---------------------------------------
__global__ void embed_kernel(const int* __restrict__ dec_input,
                             const float* __restrict__ table){
    int b = blockIdx.x, t = threadIdx.x;
    g_embed[b*EMBD + t] = table[(size_t)dec_input[b]*EMBD + t];
}

// ---------------- asymmetric fp16 2-product energy GEMM ------------------
#define MT 128
#define NTILE 128
#define KC 32
#define NCH (E/KC)                 // 32
#define ROWB 80
#define ARRB (128*ROWB)            // 10240
#define STG_BYTES (3*ARRB)         // Ahi, Alo, B per stage
#define WS_OFF (2*STG_BYTES)
#define V_OFF  (WS_OFF + 512)
#define EN_SMEM (V_OFF + 512)

__global__ __launch_bounds__(256, 2) void energy_mma(
        const float* __restrict__ enc, const float* __restrict__ attn_v){
    extern __shared__ char sm[];
    const int tid  = threadIdx.x;
    const int lane = tid & 31, wid = tid >> 5;
    const int wm = wid & 3;
    const int wn = wid >> 2;
    const int n0 = blockIdx.x * NTILE;
    const int m0 = blockIdx.y * MT;
    const int b  = m0 >> 11;

    float* wsP = (float*)(sm + WS_OFF);
    float* vP  = (float*)(sm + V_OFF);
    for (int j = tid; j < NTILE; j += 256){
        wsP[j] = g_ws_app[b*H + n0 + j];
        vP[j]  = attn_v[n0 + j];
    }

    const uint32_t smb = smem_u32(sm);
    const __half* Bg = g_w_h + (size_t)n0*E;

    const int ar = tid >> 1;
    const int kh = tid & 1;
    const float* Abase = enc + (size_t)(m0 + ar)*E + kh*16;

    auto loadB = [&](int stage, int k0){
        uint32_t stg = smb + (stage&1)*STG_BYTES + 2*ARRB;
        #pragma unroll
        for (int it = 0; it < 2; it++){
            int f = tid + it*256;
            int r = f >> 2, j = f & 3;
            cp16(stg + r*ROWB + j*16, Bg + (size_t)r*E + k0 + j*8);
        }
        cp_commit();
    };

    float areg[16];
    auto loadA = [&](int k0){
        const float4* gp = (const float4*)(Abase + k0);
        #pragma unroll
        for (int q = 0; q < 4; q++){
            float4 v = gp[q];
            areg[q*4+0] = v.x; areg[q*4+1] = v.y; areg[q*4+2] = v.z; areg[q*4+3] = v.w;
        }
    };
    auto storeA = [&](int stage){
        uint32_t off0 = (stage&1)*STG_BYTES;
        __half hb[16], lb[16];
        #pragma unroll
        for (int q = 0; q < 16; q++){
            hb[q] = __float2half(areg[q]);
            lb[q] = __float2half(areg[q] - __half2float(hb[q]));
        }
        uint32_t off = off0 + (uint32_t)ar*ROWB + kh*32;
        *(uint4*)(sm + off)              = *(uint4*)&hb[0];
        *(uint4*)(sm + off + 16)         = *(uint4*)&hb[8];
        *(uint4*)(sm + ARRB + off)       = *(uint4*)&lb[0];
        *(uint4*)(sm + ARRB + off + 16)  = *(uint4*)&lb[8];
    };

    float c[2][8][4];
    #pragma unroll
    for (int t = 0; t < 2; t++)
        #pragma unroll
        for (int j = 0; j < 8; j++)
            #pragma unroll
            for (int q = 0; q < 4; q++) c[t][j][q] = 0.f;

    loadB(0, 0);
    loadA(0);
    storeA(0);
    loadA(KC);

    for (int i = 0; i < NCH; i++){
        cp_wait0();
        __syncthreads();
        if (i + 1 < NCH){
            loadB(i+1, (i+1)*KC);
            storeA(i+1);
            if (i + 2 < NCH) loadA((i+2)*KC);
        }

        const uint32_t stg = smb + (i&1)*STG_BYTES;
        const uint32_t A0 = stg, A1 = stg + ARRB, B0 = stg + 2*ARRB;

        #pragma unroll
        for (int kk = 0; kk < 2; kk++){
            uint32_t ah[2][4], al[2][4];
            #pragma unroll
            for (int t = 0; t < 2; t++){
                int row = wm*32 + t*16 + (lane & 15);
                uint32_t off = (uint32_t)row*ROWB + (lane >> 4)*16 + kk*32;
                ldsm4(ah[t], A0 + off);
                ldsm4(al[t], A1 + off);
            }
            #pragma unroll
            for (int p = 0; p < 4; p++){
                int row = wn*64 + p*16 + ((lane >> 4) & 1)*8 + (lane & 7);
                uint32_t off = (uint32_t)row*ROWB + ((lane >> 3) & 1)*16 + kk*32;
                uint32_t rh[4];
                ldsm4(rh, B0 + off);
                #pragma unroll
                for (int t = 0; t < 2; t++){
                    mma_f16(c[t][2*p],   ah[t], rh[0], rh[1]);
                    mma_f16(c[t][2*p],   al[t], rh[0], rh[1]);
                    mma_f16(c[t][2*p+1], ah[t], rh[2], rh[3]);
                    mma_f16(c[t][2*p+1], al[t], rh[2], rh[3]);
                }
            }
        }
    }

    float p4[4] = {0.f, 0.f, 0.f, 0.f};
    #pragma unroll
    for (int t = 0; t < 2; t++)
        #pragma unroll
        for (int j = 0; j < 8; j++)
            #pragma unroll
            for (int q = 0; q < 4; q++){
                int nloc = wn*64 + j*8 + (lane & 3)*2 + (q & 1);
                float x = c[t][j][q] + wsP[nloc];
                p4[t*2 + (q >> 1)] += ftanh(x) * vP[nloc];
            }
    #pragma unroll
    for (int q = 0; q < 4; q++){
        p4[q] += __shfl_xor_sync(0xffffffffu, p4[q], 1);
        p4[q] += __shfl_xor_sync(0xffffffffu, p4[q], 2);
    }
    __syncthreads();
    float* red = (float*)(sm);
    if ((lane & 3) == 0){
        int rloc = wm*32 + (lane >> 2);
        if (wn == 0){
            red[rloc]      = p4[0];
            red[rloc + 8]  = p4[1];
            red[rloc + 16] = p4[2];
            red[rloc + 24] = p4[3];
        }
    }
    __syncthreads();
    if (wn == 1 && (lane & 3) == 0){
        int rloc = wm*32 + (lane >> 2);
        g_energy4[blockIdx.x][m0 + rloc]      = red[rloc]      + p4[0];
        g_energy4[blockIdx.x][m0 + rloc + 8]  = red[rloc + 8]  + p4[1];
        g_energy4[blockIdx.x][m0 + rloc + 16] = red[rloc + 16] + p4[2];
        g_energy4[blockIdx.x][m0 + rloc + 24] = red[rloc + 24] + p4[3];
    }
}

// ---------------- softmax over S per batch (combines 4 partials) ---------
__global__ void attn_softmax(){
    const int b = blockIdx.x, t = threadIdx.x;
    __shared__ float red[8];
    float ev[8];
    float m = -1e30f;
    #pragma unroll
    for (int q = 0; q < 8; q++){
        int idx = b*S + q*256 + t;
        float v = g_energy4[0][idx] + g_energy4[1][idx] + g_energy4[2][idx] + g_energy4[3][idx];
        ev[q] = v;
        m = fmaxf(m, v);
    }
    #pragma unroll
    for (int o = 16; o > 0; o >>= 1) m = fmaxf(m, __shfl_xor_sync(0xffffffffu, m, o));
    if ((t & 31) == 0) red[t >> 5] = m;
    __syncthreads();
    if (t == 0){ float mm = red[0]; for (int i = 1; i < 8; i++) mm = fmaxf(mm, red[i]); red[0] = mm; }
    __syncthreads();
    m = red[0];
    __syncthreads();
    float s = 0.f;
    #pragma unroll
    for (int q = 0; q < 8; q++){ ev[q] = __expf(ev[q]-m); s += ev[q]; }
    #pragma unroll
    for (int o = 16; o > 0; o >>= 1) s += __shfl_xor_sync(0xffffffffu, s, o);
    if ((t & 31) == 0) red[t >> 5] = s;
    __syncthreads();
    if (t == 0){ float ss = 0.f; for (int i = 0; i < 8; i++) ss += red[i]; red[0] = ss; }
    __syncthreads();
    float inv = 1.f / red[0];
    #pragma unroll
    for (int q = 0; q < 8; q++) g_attn[b*S + q*256 + t] = ev[q] * inv;
}

// ---------------- context[b,e] = sum_s attn[b,s]*enc[b,s,e] --------------
__global__ void context_kernel(const float* __restrict__ enc){
    const int b = blockIdx.x, ec = blockIdx.y, sc = blockIdx.z;
    __shared__ float a_s[512];
    const int t = threadIdx.x;
    for (int i = t; i < 512; i += 256) a_s[i] = g_attn[b*S + sc*512 + i];
    __syncthreads();
    const int e = ec*256 + t;
    const float* base = enc + ((size_t)b*S + sc*512)*E + e;
    float acc = 0.f;
    #pragma unroll 4
    for (int s = 0; s < 512; s++) acc = fmaf(a_s[s], base[(size_t)s*E], acc);
    atomicAdd(&g_context[b*E + e], acc);
}

// ---------------- LSTM gates GEMM (K-split x4) ---------------------------
__global__ __launch_bounds__(256) void gates_gemm(
        const float* __restrict__ h0,
        const float* __restrict__ w_ih,
        const float* __restrict__ w_hh){
    __shared__ float Xs[16][65];
    __shared__ float Ws[16][65];
    const int n0 = blockIdx.x * 64;
    const int ks = blockIdx.y;            // K split 0..3, 448 each
    const int tid = threadIdx.x;
    const int tx = tid & 15, ty = tid >> 4;
    float acc[4][4];
    #pragma unroll
    for (int i = 0; i < 4; i++)
        #pragma unroll
        for (int j = 0; j < 4; j++) acc[i][j] = 0.f;

    for (int k0 = ks*448; k0 < (ks+1)*448; k0 += 16) {
        for (int i = tid; i < 64*16; i += 256){
            int m = i >> 4, kk = i & 15, k = k0 + kk;
            float xv;
            if (k < E)            xv = g_context[m*E + k];
            else if (k < E+EMBD)  xv = g_embed[m*EMBD + (k - E)];
            else                  xv = h0[m*H + (k - E - EMBD)];
            Xs[kk][m] = xv;
        }
        for (int i = tid; i < 64*16; i += 256){
            int nn = i >> 4, kk = i & 15, k = k0 + kk, n = n0 + nn;
            float wv = (k < E+EMBD) ? w_ih[(size_t)n*(E+EMBD) + k]
                                    : w_hh[(size_t)n*H + (k - E - EMBD)];
            Ws[kk][nn] = wv;
        }
        __syncthreads();
        #pragma unroll
        for (int kk = 0; kk < 16; kk++){
            float ra[4], rb[4];
            #pragma unroll
            for (int i = 0; i < 4; i++) ra[i] = Xs[kk][ty*4+i];
            #pragma unroll
            for (int j = 0; j < 4; j++) rb[j] = Ws[kk][tx*4+j];
            #pragma unroll
            for (int i = 0; i < 4; i++)
                #pragma unroll
                for (int j = 0; j < 4; j++) acc[i][j] = fmaf(ra[i], rb[j], acc[i][j]);
        }
        __syncthreads();
    }
    #pragma unroll
    for (int i = 0; i < 4; i++)
        #pragma unroll
        for (int j = 0; j < 4; j++){
            int m = ty*4+i, n = n0 + tx*4+j;
            g_gates4[ks][m*(4*H) + n] = acc[i][j];
        }
}

// ---------------- LSTM pointwise (sums gate partials; emits fp16 h_t) ----
__global__ void lstm_kernel(const float* __restrict__ c0,
                            const float* __restrict__ b_ih,
                            const float* __restrict__ b_hh,
                            float* __restrict__ out){
    const int b = blockIdx.x, h = threadIdx.x;
    const int base = b*(4*H);
    float gi = 0.f, gf = 0.f, gg = 0.f, go = 0.f;
    #pragma unroll
    for (int p = 0; p < 4; p++){
        const float* gp = g_gates4[p] + base;
        gi += gp[h];
        gf += gp[H + h];
        gg += gp[2*H + h];
        go += gp[3*H + h];
    }
    gi += b_ih[h]       + b_hh[h];
    gf += b_ih[H + h]   + b_hh[H + h];
    gg += b_ih[2*H + h] + b_hh[2*H + h];
    go += b_ih[3*H + h] + b_hh[3*H + h];
    float ig = sigf(gi);
    float fg = sigf(gf);
    float gv = tanhf(gg);
    float og = sigf(go);
    float c  = fg * c0[b*H + h] + ig * gv;
    float ht = og * tanhf(c);
    out[OUT_HT + b*H + h] = ht;
    out[OUT_CT + b*H + h] = c;
    __half hh = __float2half(ht);
    g_ht_hi[b*H + h] = hh;
    g_ht_lo[b*H + h] = __float2half(ht - __half2float(hh));
}

// ---------------- logits via fp16 2-product HMMA -------------------------
#define LKC 32
#define LCH (H/LKC)                // 16
#define LRB 80
#define LH_ARR (64*LRB)            // 5120
#define LW_ARR (128*LRB)           // 10240
#define LSTG (2*LH_ARR + LW_ARR)   // 20480

__global__ __launch_bounds__(256) void logits_mma(const float* __restrict__ vb){
    __shared__ char sm2[2*LSTG];
    const int tid  = threadIdx.x;
    const int lane = tid & 31, wid = tid >> 5;
    const int wm = wid & 3;
    const int wn = wid >> 2;
    const int n0 = blockIdx.x * 128;
    const uint32_t smb = smem_u32(sm2);

    auto loadAB = [&](int i){
        uint32_t stg = smb + (i&1)*LSTG;
        int k0 = i*LKC;
        #pragma unroll
        for (int it = 0; it < 4; it++){
            int f = tid + it*256;
            if (f < 512){
                int digit = f >> 8, idx = f & 255;
                int r = idx >> 2, j = idx & 3;
                const __half* src = (digit ? g_ht_lo : g_ht_hi) + r*H + k0 + j*8;
                cp16(stg + digit*LH_ARR + r*LRB + j*16, src);
            } else {
                int idx = f - 512;
                int r = idx >> 2, j = idx & 3;
                int rg = n0 + r; if (rg >= V) rg = V - 1;
                cp16(stg + 2*LH_ARR + r*LRB + j*16,
                     g_vw_h + (size_t)rg*H + k0 + j*8);
            }
        }
        cp_commit();
    };

    float c[8][4];
    #pragma unroll
    for (int j = 0; j < 8; j++)
        #pragma unroll
        for (int q = 0; q < 4; q++) c[j][q] = 0.f;

    loadAB(0);

    for (int i = 0; i < LCH; i++){
        cp_wait0();
        __syncthreads();
        if (i + 1 < LCH) loadAB(i+1);

        const uint32_t stg = smb + (i&1)*LSTG;
        const uint32_t A0 = stg, A1 = stg + LH_ARR, B0 = stg + 2*LH_ARR;

        #pragma unroll
        for (int kk = 0; kk < 2; kk++){
            uint32_t ah[4], al[4];
            {
                int row = wm*16 + (lane & 15);
                uint32_t off = (uint32_t)row*LRB + (lane >> 4)*16 + kk*32;
                ldsm4(ah, A0 + off);
                ldsm4(al, A1 + off);
            }
            #pragma unroll
            for (int p = 0; p < 4; p++){
                int row = wn*64 + p*16 + ((lane >> 4) & 1)*8 + (lane & 7);
                uint32_t off = (uint32_t)row*LRB + ((lane >> 3) & 1)*16 + kk*32;
                uint32_t rh[4];
                ldsm4(rh, B0 + off);
                mma_f16(c[2*p],   ah, rh[0], rh[1]);
                mma_f16(c[2*p],   al, rh[0], rh[1]);
                mma_f16(c[2*p+1], ah, rh[2], rh[3]);
                mma_f16(c[2*p+1], al, rh[2], rh[3]);
            }
        }
    }

    #pragma unroll
    for (int j = 0; j < 8; j++)
        #pragma unroll
        for (int q = 0; q < 4; q++){
            int m = wm*16 + (lane >> 2) + (q >> 1)*8;
            int v = n0 + wn*64 + j*8 + (lane & 3)*2 + (q & 1);
            if (v < V) g_logits[(size_t)m*V + v] = c[j][q] + vb[v];
        }
}

// ---------------- p_gen ---------------------------------------------------
__global__ void pgen_kernel(const float* __restrict__ ht,
                            const float* __restrict__ wh_vec,
                            const float* __restrict__ ws_vec,
                            const float* __restrict__ wx_vec){
    const int b = blockIdx.x, t = threadIdx.x;
    __shared__ float red[8];
    float acc = 0.f;
    for (int i = t; i < E;    i += 256) acc += g_context[b*E + i]   * wh_vec[i];
    for (int i = t; i < H;    i += 256) acc += ht[b*H + i]          * ws_vec[i];
    for (int i = t; i < EMBD; i += 256) acc += g_embed[b*EMBD + i]  * wx_vec[i];
    #pragma unroll
    for (int o = 16; o > 0; o >>= 1) acc += __shfl_xor_sync(0xffffffffu, acc, o);
    if ((t & 31) == 0) red[t >> 5] = acc;
    __syncthreads();
    if (t == 0){
        float s = 0.f;
        for (int i = 0; i < 8; i++) s += red[i];
        g_pgen[b] = sigf(s);
    }
}

// ---------------- vocab softmax * p_gen -> out (online 2-pass) -----------
__global__ void vocab_out_kernel(float* __restrict__ out){
    const int b = blockIdx.x, t = threadIdx.x;   // 1024 threads
    const int lane = t & 31, wrp = t >> 5;
    __shared__ float redm[32], reds[32], fin[2];
    const float* row = g_logits + (size_t)b*V;

    // pass 1: online max+sum
    float m = -1e30f, s = 0.f;
    for (int v = t; v < V; v += 1024){
        float x = row[v];
        if (x > m){ s = s*__expf(m - x) + 1.f; m = x; }
        else        s += __expf(x - m);
    }
    #pragma unroll
    for (int o = 16; o > 0; o >>= 1){
        float mo = __shfl_xor_sync(0xffffffffu, m, o);
        float so = __shfl_xor_sync(0xffffffffu, s, o);
        float M = fmaxf(m, mo);
        s = s*__expf(m - M) + so*__expf(mo - M);
        m = M;
    }
    if (lane == 0){ redm[wrp] = m; reds[wrp] = s; }
    __syncthreads();
    if (t < 32){
        float mm = redm[t], ss = reds[t];
        #pragma unroll
        for (int o = 16; o > 0; o >>= 1){
            float mo = __shfl_xor_sync(0xffffffffu, mm, o);
            float so = __shfl_xor_sync(0xffffffffu, ss, o);
            float M = fmaxf(mm, mo);
            ss = ss*__expf(mm - M) + so*__expf(mo - M);
            mm = M;
        }
        if (t == 0){ fin[0] = mm; fin[1] = g_pgen[b] / ss; }
    }
    __syncthreads();
    const float M = fin[0], scale = fin[1];
    // pass 2: write
    for (int v = t; v < V; v += 1024)
        out[(size_t)b*V + v] = __expf(row[v] - M) * scale;
}

// ---------------- copy-mechanism scatter ---------------------------------
__global__ void scatter_kernel(const int* __restrict__ enc_inputs,
                               float* __restrict__ out){
    const int idx = blockIdx.x*256 + threadIdx.x;
    if (idx >= MTOT) return;
    const int b = idx >> 11;
    const int tok = enc_inputs[idx];
    atomicAdd(&out[(size_t)b*V + tok], (1.f - g_pgen[b]) * g_attn[idx]);
}

// ---------------- launch --------------------------------------------------
extern "C" void kernel_launch(void* const* d_in, const int* in_sizes, int n_in,
                              void* d_out, int out_size) {
    const float* enc_out   = (const float*)d_in[0];
    const float* h0        = (const float*)d_in[1];
    const float* c0        = (const float*)d_in[2];
    const int*   dec_input = (const int*)  d_in[3];
    const int*   enc_inputs= (const int*)  d_in[4];
    const float* embed_tab = (const float*)d_in[5];
    const float* attn_wh_w = (const float*)d_in[6];
    const float* attn_wh_b = (const float*)d_in[7];
    const float* attn_ws_w = (const float*)d_in[8];
    const float* attn_ws_b = (const float*)d_in[9];
    const float* attn_v    = (const float*)d_in[10];
    const float* lstm_w_ih = (const float*)d_in[11];
    const float* lstm_w_hh = (const float*)d_in[12];
    const float* lstm_b_ih = (const float*)d_in[13];
    const float* lstm_b_hh = (const float*)d_in[14];
    const float* wh_vec    = (const float*)d_in[15];
    const float* ws_vec    = (const float*)d_in[16];
    const float* wx_vec    = (const float*)d_in[17];
    const float* v_w       = (const float*)d_in[18];
    const float* v_b       = (const float*)d_in[19];
    float* out = (float*)d_out;
    const float* ht = out + OUT_HT;

    static bool attr_set = false;
    if (!attr_set){
        cudaFuncSetAttribute(energy_mma, cudaFuncAttributeMaxDynamicSharedMemorySize, EN_SMEM);
        attr_set = true;
    }

    // energy_mma kept as the 4th launch (ncu capture slot)
    conv_w_kernel<<<2048, 256>>>(attn_wh_w);
    wsapp_kernel<<<dim3(B, 64), 256>>>(h0, attn_ws_w, attn_ws_b, attn_wh_b);
    conv_vw_kernel<<<12565, 256>>>(v_w);
    energy_mma<<<dim3(H/NTILE, MTOT/MT), 256, EN_SMEM>>>(enc_out, attn_v);
    zero_kernel<<<256, 256>>>();
    embed_kernel<<<B, 256>>>(dec_input, embed_tab);
    attn_softmax<<<B, 256>>>();
    context_kernel<<<dim3(B, 4, 4), 256>>>(enc_out);
    gates_gemm<<<dim3((4*H)/64, 4), 256>>>(h0, lstm_w_ih, lstm_w_hh);
    lstm_kernel<<<B, 512>>>(c0, lstm_b_ih, lstm_b_hh, out);
    logits_mma<<<(V + 127)/128, 256>>>(v_b);
    pgen_kernel<<<B, 256>>>(ht, wh_vec, ws_vec, wx_vec);
    vocab_out_kernel<<<B, 1024>>>(out);
    scatter_kernel<<<(MTOT + 255)/256, 256>>>(enc_inputs, out);
}

// round 14
// speedup vs baseline: 4.1130x; 1.0329x over previous
#include <cuda_runtime.h>
#include <cuda_fp16.h>
#include <math.h>
#include <stdint.h>

#define B 64
#define S 2048
#define E 1024
#define H 512
#define EMBD 256
#define V 50257
#define MTOT (B*S)

#define OUT_HT ((size_t)B*V)
#define OUT_CT (OUT_HT + (size_t)B*H)

// ---------------- device scratch (no allocations allowed) ----------------
__device__ float g_ws_app[B*H];
__device__ float g_energy4[4][MTOT];
__device__ float g_attn[MTOT];
__device__ float g_context[B*E];
__device__ float g_embed[B*EMBD];
__device__ float g_gates4[4][B*4*H];
__device__ float g_logits[(size_t)B*V];
__device__ float g_pgen[B];

__device__ __half g_w_h[H*E];          // attn_wh_w fp16
__device__ __half g_ht_hi[B*H];        // h_t fp16 hi
__device__ __half g_ht_lo[B*H];        // h_t fp16 lo

__device__ __forceinline__ float sigf(float x){ return 1.f/(1.f+__expf(-x)); }
__device__ __forceinline__ float ftanh(float x){
    x = fminf(fmaxf(x, -15.f), 15.f);
    float e2 = __expf(2.f*x);
    return (e2 - 1.f) / (e2 + 1.f);
}

// ======================= portable PTX helpers =============================
__device__ __forceinline__ uint32_t smem_u32(const void* p){
    uint32_t a;
    asm("{ .reg .u64 t; cvta.to.shared.u64 t, %1; cvt.u32.u64 %0, t; }" : "=r"(a) : "l"(p));
    return a;
}
__device__ __forceinline__ void cp16(uint32_t dst, const void* src){
    asm volatile("cp.async.cg.shared.global [%0], [%1], 16;" :: "r"(dst), "l"(src));
}
__device__ __forceinline__ void cp_commit(){ asm volatile("cp.async.commit_group;" ::: "memory"); }
__device__ __forceinline__ void cp_wait0(){ asm volatile("cp.async.wait_group 0;" ::: "memory"); }

__device__ __forceinline__ void ldsm4(uint32_t* r, uint32_t addr){
    asm volatile("ldmatrix.sync.aligned.m8n8.x4.shared.b16 {%0,%1,%2,%3}, [%4];"
        : "=r"(r[0]), "=r"(r[1]), "=r"(r[2]), "=r"(r[3]) : "r"(addr));
}
__device__ __forceinline__ void mma_f16(float* c, const uint32_t* a, uint32_t b0, uint32_t b1){
    asm volatile("mma.sync.aligned.m16n8k16.row.col.f32.f16.f16.f32 "
        "{%0,%1,%2,%3}, {%4,%5,%6,%7}, {%8,%9}, {%0,%1,%2,%3};"
        : "+f"(c[0]), "+f"(c[1]), "+f"(c[2]), "+f"(c[3])
        : "r"(a[0]), "r"(a[1]), "r"(a[2]), "r"(a[3]), "r"(b0), "r"(b1));
}

// ---------------- fp16 conversion for attn weights ------------------------
__global__ void conv_w_kernel(const float* __restrict__ src){
    int i = blockIdx.x*256 + threadIdx.x;
    g_w_h[i] = __float2half(src[i]);
}

// ---------------- init: zero context + embedding lookup ------------------
__global__ void init_kernel(const int* __restrict__ dec_input,
                            const float* __restrict__ table){
    int i = blockIdx.x*256 + threadIdx.x;      // grid 256 -> 65536
    if (i < B*E) g_context[i] = 0.f;
    if (i < B*EMBD){
        int b = i >> 8, t = i & 255;
        g_embed[i] = table[(size_t)dec_input[b]*EMBD + t];
    }
}

// ---------------- ws_app[b,n] = h0[b]·ws_w[n] + ws_b[n] + wh_b[n] --------
__global__ void wsapp_kernel(const float* __restrict__ h0,
                             const float* __restrict__ ws_w,
                             const float* __restrict__ ws_b,
                             const float* __restrict__ wh_b){
    __shared__ float hs[H];
    const int b = blockIdx.x, tid = threadIdx.x;
    for (int i = tid; i < H; i += 256) hs[i] = h0[b*H + i];
    __syncthreads();
    const int warp = tid >> 5, lane = tid & 31;
    const int n = blockIdx.y * 8 + warp;
    const float* wrow = ws_w + (size_t)n*H;
    float acc = 0.f;
    #pragma unroll
    for (int k = lane*4; k < H; k += 128){
        float4 w = *(const float4*)(wrow + k);
        acc += hs[k]*w.x + hs[k+1]*w.y + hs[k+2]*w.z + hs[k+3]*w.w;
    }
    #pragma unroll
    for (int o = 16; o > 0; o >>= 1) acc += __shfl_xor_sync(0xffffffffu, acc, o);
    if (lane == 0) g_ws_app[b*H + n] = acc + ws_b[n] + wh_b[n];
}

// ---------------- asymmetric fp16 2-product energy GEMM (unchanged) ------
#define MT 128
#define NTILE 128
#define KC 32
#define NCH (E/KC)
#define ROWB 80
#define ARRB (128*ROWB)
#define STG_BYTES (3*ARRB)
#define WS_OFF (2*STG_BYTES)
#define V_OFF  (WS_OFF + 512)
#define EN_SMEM (V_OFF + 512)

__global__ __launch_bounds__(256, 2) void energy_mma(
        const float* __restrict__ enc, const float* __restrict__ attn_v){
    extern __shared__ char sm[];
    const int tid  = threadIdx.x;
    const int lane = tid & 31, wid = tid >> 5;
    const int wm = wid & 3;
    const int wn = wid >> 2;
    const int n0 = blockIdx.x * NTILE;
    const int m0 = blockIdx.y * MT;
    const int b  = m0 >> 11;

    float* wsP = (float*)(sm + WS_OFF);
    float* vP  = (float*)(sm + V_OFF);
    for (int j = tid; j < NTILE; j += 256){
        wsP[j] = g_ws_app[b*H + n0 + j];
        vP[j]  = attn_v[n0 + j];
    }

    const uint32_t smb = smem_u32(sm);
    const __half* Bg = g_w_h + (size_t)n0*E;

    const int ar = tid >> 1;
    const int kh = tid & 1;
    const float* Abase = enc + (size_t)(m0 + ar)*E + kh*16;

    auto loadB = [&](int stage, int k0){
        uint32_t stg = smb + (stage&1)*STG_BYTES + 2*ARRB;
        #pragma unroll
        for (int it = 0; it < 2; it++){
            int f = tid + it*256;
            int r = f >> 2, j = f & 3;
            cp16(stg + r*ROWB + j*16, Bg + (size_t)r*E + k0 + j*8);
        }
        cp_commit();
    };

    float areg[16];
    auto loadA = [&](int k0){
        const float4* gp = (const float4*)(Abase + k0);
        #pragma unroll
        for (int q = 0; q < 4; q++){
            float4 v = gp[q];
            areg[q*4+0] = v.x; areg[q*4+1] = v.y; areg[q*4+2] = v.z; areg[q*4+3] = v.w;
        }
    };
    auto storeA = [&](int stage){
        uint32_t off0 = (stage&1)*STG_BYTES;
        __half hb[16], lb[16];
        #pragma unroll
        for (int q = 0; q < 16; q++){
            hb[q] = __float2half(areg[q]);
            lb[q] = __float2half(areg[q] - __half2float(hb[q]));
        }
        uint32_t off = off0 + (uint32_t)ar*ROWB + kh*32;
        *(uint4*)(sm + off)              = *(uint4*)&hb[0];
        *(uint4*)(sm + off + 16)         = *(uint4*)&hb[8];
        *(uint4*)(sm + ARRB + off)       = *(uint4*)&lb[0];
        *(uint4*)(sm + ARRB + off + 16)  = *(uint4*)&lb[8];
    };

    float c[2][8][4];
    #pragma unroll
    for (int t = 0; t < 2; t++)
        #pragma unroll
        for (int j = 0; j < 8; j++)
            #pragma unroll
            for (int q = 0; q < 4; q++) c[t][j][q] = 0.f;

    loadB(0, 0);
    loadA(0);
    storeA(0);
    loadA(KC);

    for (int i = 0; i < NCH; i++){
        cp_wait0();
        __syncthreads();
        if (i + 1 < NCH){
            loadB(i+1, (i+1)*KC);
            storeA(i+1);
            if (i + 2 < NCH) loadA((i+2)*KC);
        }

        const uint32_t stg = smb + (i&1)*STG_BYTES;
        const uint32_t A0 = stg, A1 = stg + ARRB, B0 = stg + 2*ARRB;

        #pragma unroll
        for (int kk = 0; kk < 2; kk++){
            uint32_t ah[2][4], al[2][4];
            #pragma unroll
            for (int t = 0; t < 2; t++){
                int row = wm*32 + t*16 + (lane & 15);
                uint32_t off = (uint32_t)row*ROWB + (lane >> 4)*16 + kk*32;
                ldsm4(ah[t], A0 + off);
                ldsm4(al[t], A1 + off);
            }
            #pragma unroll
            for (int p = 0; p < 4; p++){
                int row = wn*64 + p*16 + ((lane >> 4) & 1)*8 + (lane & 7);
                uint32_t off = (uint32_t)row*ROWB + ((lane >> 3) & 1)*16 + kk*32;
                uint32_t rh[4];
                ldsm4(rh, B0 + off);
                #pragma unroll
                for (int t = 0; t < 2; t++){
                    mma_f16(c[t][2*p],   ah[t], rh[0], rh[1]);
                    mma_f16(c[t][2*p],   al[t], rh[0], rh[1]);
                    mma_f16(c[t][2*p+1], ah[t], rh[2], rh[3]);
                    mma_f16(c[t][2*p+1], al[t], rh[2], rh[3]);
                }
            }
        }
    }

    float p4[4] = {0.f, 0.f, 0.f, 0.f};
    #pragma unroll
    for (int t = 0; t < 2; t++)
        #pragma unroll
        for (int j = 0; j < 8; j++)
            #pragma unroll
            for (int q = 0; q < 4; q++){
                int nloc = wn*64 + j*8 + (lane & 3)*2 + (q & 1);
                float x = c[t][j][q] + wsP[nloc];
                p4[t*2 + (q >> 1)] += ftanh(x) * vP[nloc];
            }
    #pragma unroll
    for (int q = 0; q < 4; q++){
        p4[q] += __shfl_xor_sync(0xffffffffu, p4[q], 1);
        p4[q] += __shfl_xor_sync(0xffffffffu, p4[q], 2);
    }
    __syncthreads();
    float* red = (float*)(sm);
    if ((lane & 3) == 0){
        int rloc = wm*32 + (lane >> 2);
        if (wn == 0){
            red[rloc]      = p4[0];
            red[rloc + 8]  = p4[1];
            red[rloc + 16] = p4[2];
            red[rloc + 24] = p4[3];
        }
    }
    __syncthreads();
    if (wn == 1 && (lane & 3) == 0){
        int rloc = wm*32 + (lane >> 2);
        g_energy4[blockIdx.x][m0 + rloc]      = red[rloc]      + p4[0];
        g_energy4[blockIdx.x][m0 + rloc + 8]  = red[rloc + 8]  + p4[1];
        g_energy4[blockIdx.x][m0 + rloc + 16] = red[rloc + 16] + p4[2];
        g_energy4[blockIdx.x][m0 + rloc + 24] = red[rloc + 24] + p4[3];
    }
}

// ---------------- softmax over S per batch -------------------------------
__global__ void attn_softmax(){
    const int b = blockIdx.x, t = threadIdx.x;
    __shared__ float red[8];
    float ev[8];
    float m = -1e30f;
    #pragma unroll
    for (int q = 0; q < 8; q++){
        int idx = b*S + q*256 + t;
        float v = g_energy4[0][idx] + g_energy4[1][idx] + g_energy4[2][idx] + g_energy4[3][idx];
        ev[q] = v;
        m = fmaxf(m, v);
    }
    #pragma unroll
    for (int o = 16; o > 0; o >>= 1) m = fmaxf(m, __shfl_xor_sync(0xffffffffu, m, o));
    if ((t & 31) == 0) red[t >> 5] = m;
    __syncthreads();
    if (t == 0){ float mm = red[0]; for (int i = 1; i < 8; i++) mm = fmaxf(mm, red[i]); red[0] = mm; }
    __syncthreads();
    m = red[0];
    __syncthreads();
    float s = 0.f;
    #pragma unroll
    for (int q = 0; q < 8; q++){ ev[q] = __expf(ev[q]-m); s += ev[q]; }
    #pragma unroll
    for (int o = 16; o > 0; o >>= 1) s += __shfl_xor_sync(0xffffffffu, s, o);
    if ((t & 31) == 0) red[t >> 5] = s;
    __syncthreads();
    if (t == 0){ float ss = 0.f; for (int i = 0; i < 8; i++) ss += red[i]; red[0] = ss; }
    __syncthreads();
    float inv = 1.f / red[0];
    #pragma unroll
    for (int q = 0; q < 8; q++) g_attn[b*S + q*256 + t] = ev[q] * inv;
}

// ---------------- context[b,e] = sum_s attn[b,s]*enc[b,s,e] --------------
__global__ void context_kernel(const float* __restrict__ enc){
    const int b = blockIdx.x, ec = blockIdx.y, sc = blockIdx.z;
    __shared__ float a_s[512];
    const int t = threadIdx.x;
    for (int i = t; i < 512; i += 256) a_s[i] = g_attn[b*S + sc*512 + i];
    __syncthreads();
    const int e = ec*256 + t;
    const float* base = enc + ((size_t)b*S + sc*512)*E + e;
    float acc = 0.f;
    #pragma unroll 4
    for (int s = 0; s < 512; s++) acc = fmaf(a_s[s], base[(size_t)s*E], acc);
    atomicAdd(&g_context[b*E + e], acc);
}

// ---------------- LSTM gates GEMM (K-split x4) ---------------------------
__global__ __launch_bounds__(256) void gates_gemm(
        const float* __restrict__ h0,
        const float* __restrict__ w_ih,
        const float* __restrict__ w_hh){
    __shared__ float Xs[16][65];
    __shared__ float Ws[16][65];
    const int n0 = blockIdx.x * 64;
    const int ks = blockIdx.y;
    const int tid = threadIdx.x;
    const int tx = tid & 15, ty = tid >> 4;
    float acc[4][4];
    #pragma unroll
    for (int i = 0; i < 4; i++)
        #pragma unroll
        for (int j = 0; j < 4; j++) acc[i][j] = 0.f;

    for (int k0 = ks*448; k0 < (ks+1)*448; k0 += 16) {
        for (int i = tid; i < 64*16; i += 256){
            int m = i >> 4, kk = i & 15, k = k0 + kk;
            float xv;
            if (k < E)            xv = g_context[m*E + k];
            else if (k < E+EMBD)  xv = g_embed[m*EMBD + (k - E)];
            else                  xv = h0[m*H + (k - E - EMBD)];
            Xs[kk][m] = xv;
        }
        for (int i = tid; i < 64*16; i += 256){
            int nn = i >> 4, kk = i & 15, k = k0 + kk, n = n0 + nn;
            float wv = (k < E+EMBD) ? w_ih[(size_t)n*(E+EMBD) + k]
                                    : w_hh[(size_t)n*H + (k - E - EMBD)];
            Ws[kk][nn] = wv;
        }
        __syncthreads();
        #pragma unroll
        for (int kk = 0; kk < 16; kk++){
            float ra[4], rb[4];
            #pragma unroll
            for (int i = 0; i < 4; i++) ra[i] = Xs[kk][ty*4+i];
            #pragma unroll
            for (int j = 0; j < 4; j++) rb[j] = Ws[kk][tx*4+j];
            #pragma unroll
            for (int i = 0; i < 4; i++)
                #pragma unroll
                for (int j = 0; j < 4; j++) acc[i][j] = fmaf(ra[i], rb[j], acc[i][j]);
        }
        __syncthreads();
    }
    #pragma unroll
    for (int i = 0; i < 4; i++)
        #pragma unroll
        for (int j = 0; j < 4; j++){
            int m = ty*4+i, n = n0 + tx*4+j;
            g_gates4[ks][m*(4*H) + n] = acc[i][j];
        }
}

// ---------------- LSTM pointwise + p_gen (fused) -------------------------
__global__ void lstm_kernel(const float* __restrict__ c0,
                            const float* __restrict__ b_ih,
                            const float* __restrict__ b_hh,
                            const float* __restrict__ wh_vec,
                            const float* __restrict__ ws_vec,
                            const float* __restrict__ wx_vec,
                            float* __restrict__ out){
    __shared__ float red[16];
    const int b = blockIdx.x, h = threadIdx.x;   // 512 threads
    const int base = b*(4*H);
    float gi = 0.f, gf = 0.f, gg = 0.f, go = 0.f;
    #pragma unroll
    for (int p = 0; p < 4; p++){
        const float* gp = g_gates4[p] + base;
        gi += gp[h];
        gf += gp[H + h];
        gg += gp[2*H + h];
        go += gp[3*H + h];
    }
    gi += b_ih[h]       + b_hh[h];
    gf += b_ih[H + h]   + b_hh[H + h];
    gg += b_ih[2*H + h] + b_hh[2*H + h];
    go += b_ih[3*H + h] + b_hh[3*H + h];
    float ig = sigf(gi);
    float fg = sigf(gf);
    float gv = tanhf(gg);
    float og = sigf(go);
    float c  = fg * c0[b*H + h] + ig * gv;
    float ht = og * tanhf(c);
    out[OUT_HT + b*H + h] = ht;
    out[OUT_CT + b*H + h] = c;
    __half hh = __float2half(ht);
    g_ht_hi[b*H + h] = hh;
    g_ht_lo[b*H + h] = __float2half(ht - __half2float(hh));

    // fused p_gen: context·wh + ht·ws + embed·wx
    float acc = ht * ws_vec[h];
    acc += g_context[b*E + h]       * wh_vec[h];
    acc += g_context[b*E + h + 512] * wh_vec[h + 512];
    if (h < EMBD) acc += g_embed[b*EMBD + h] * wx_vec[h];
    #pragma unroll
    for (int o = 16; o > 0; o >>= 1) acc += __shfl_xor_sync(0xffffffffu, acc, o);
    if ((h & 31) == 0) red[h >> 5] = acc;
    __syncthreads();
    if (h == 0){
        float s = 0.f;
        for (int i = 0; i < 16; i++) s += red[i];
        g_pgen[b] = sigf(s);
    }
}

// ---------------- logits via fp16 2-product HMMA (v_w fp32 in-kernel) ----
#define LKC 32
#define LCH (H/LKC)                // 16
#define LRB 80
#define LH_ARR (64*LRB)            // 5120
#define LW_ARR (128*LRB)           // 10240
#define LSTG (2*LH_ARR + LW_ARR)   // 20480

__global__ __launch_bounds__(256) void logits_mma(
        const float* __restrict__ vw, const float* __restrict__ vb){
    __shared__ char sm2[2*LSTG];
    const int tid  = threadIdx.x;
    const int lane = tid & 31, wid = tid >> 5;
    const int wm = wid & 3;
    const int wn = wid >> 2;
    const int n0 = blockIdx.x * 128;
    const uint32_t smb = smem_u32(sm2);

    // A (h_t hi/lo) via cp.async
    auto loadA_cp = [&](int i){
        uint32_t stg = smb + (i&1)*LSTG;
        int k0 = i*LKC;
        #pragma unroll
        for (int it = 0; it < 2; it++){
            int f = tid + it*256;              // 0..511
            int digit = f >> 8, idx = f & 255;
            int r = idx >> 2, j = idx & 3;
            const __half* src = (digit ? g_ht_lo : g_ht_hi) + r*H + k0 + j*8;
            cp16(stg + digit*LH_ARR + r*LRB + j*16, src);
        }
        cp_commit();
    };

    // B (v_w fp32) via register double-buffer + in-register fp16 convert
    const int br = tid >> 1;                    // row 0..127
    const int bkh = tid & 1;                    // k-half
    int rg = n0 + br; if (rg >= V) rg = V - 1;
    const float* Bbase = vw + (size_t)rg*H + bkh*16;

    float breg[16];
    auto loadB = [&](int k0){
        const float4* gp = (const float4*)(Bbase + k0);
        #pragma unroll
        for (int q = 0; q < 4; q++){
            float4 v = gp[q];
            breg[q*4+0] = v.x; breg[q*4+1] = v.y; breg[q*4+2] = v.z; breg[q*4+3] = v.w;
        }
    };
    auto storeB = [&](int stage){
        __half hb[16];
        #pragma unroll
        for (int q = 0; q < 16; q++) hb[q] = __float2half(breg[q]);
        uint32_t off = (stage&1)*LSTG + 2*LH_ARR + (uint32_t)br*LRB + bkh*32;
        *(uint4*)(sm2 + off)      = *(uint4*)&hb[0];
        *(uint4*)(sm2 + off + 16) = *(uint4*)&hb[8];
    };

    float c[8][4];
    #pragma unroll
    for (int j = 0; j < 8; j++)
        #pragma unroll
        for (int q = 0; q < 4; q++) c[j][q] = 0.f;

    loadA_cp(0);
    loadB(0);
    storeB(0);
    loadB(LKC);

    for (int i = 0; i < LCH; i++){
        cp_wait0();
        __syncthreads();
        if (i + 1 < LCH){
            loadA_cp(i+1);
            storeB(i+1);
            if (i + 2 < LCH) loadB((i+2)*LKC);
        }

        const uint32_t stg = smb + (i&1)*LSTG;
        const uint32_t A0 = stg, A1 = stg + LH_ARR, B0 = stg + 2*LH_ARR;

        #pragma unroll
        for (int kk = 0; kk < 2; kk++){
            uint32_t ah[4], al[4];
            {
                int row = wm*16 + (lane & 15);
                uint32_t off = (uint32_t)row*LRB + (lane >> 4)*16 + kk*32;
                ldsm4(ah, A0 + off);
                ldsm4(al, A1 + off);
            }
            #pragma unroll
            for (int p = 0; p < 4; p++){
                int row = wn*64 + p*16 + ((lane >> 4) & 1)*8 + (lane & 7);
                uint32_t off = (uint32_t)row*LRB + ((lane >> 3) & 1)*16 + kk*32;
                uint32_t rh[4];
                ldsm4(rh, B0 + off);
                mma_f16(c[2*p],   ah, rh[0], rh[1]);
                mma_f16(c[2*p],   al, rh[0], rh[1]);
                mma_f16(c[2*p+1], ah, rh[2], rh[3]);
                mma_f16(c[2*p+1], al, rh[2], rh[3]);
            }
        }
    }

    #pragma unroll
    for (int j = 0; j < 8; j++)
        #pragma unroll
        for (int q = 0; q < 4; q++){
            int m = wm*16 + (lane >> 2) + (q >> 1)*8;
            int v = n0 + wn*64 + j*8 + (lane & 3)*2 + (q & 1);
            if (v < V) g_logits[(size_t)m*V + v] = c[j][q] + vb[v];
        }
}

// ---------------- vocab softmax * p_gen -> out (online) ------------------
__global__ void vocab_out_kernel(float* __restrict__ out){
    const int b = blockIdx.x, t = threadIdx.x;   // 1024 threads
    const int lane = t & 31, wrp = t >> 5;
    __shared__ float redm[32], reds[32], fin[2];
    const float* row = g_logits + (size_t)b*V;

    float m = -1e30f, s = 0.f;
    for (int v = t; v < V; v += 1024){
        float x = row[v];
        if (x > m){ s = s*__expf(m - x) + 1.f; m = x; }
        else        s += __expf(x - m);
    }
    #pragma unroll
    for (int o = 16; o > 0; o >>= 1){
        float mo = __shfl_xor_sync(0xffffffffu, m, o);
        float so = __shfl_xor_sync(0xffffffffu, s, o);
        float M = fmaxf(m, mo);
        s = s*__expf(m - M) + so*__expf(mo - M);
        m = M;
    }
    if (lane == 0){ redm[wrp] = m; reds[wrp] = s; }
    __syncthreads();
    if (t < 32){
        float mm = redm[t], ss = reds[t];
        #pragma unroll
        for (int o = 16; o > 0; o >>= 1){
            float mo = __shfl_xor_sync(0xffffffffu, mm, o);
            float so = __shfl_xor_sync(0xffffffffu, ss, o);
            float M = fmaxf(mm, mo);
            ss = ss*__expf(mm - M) + so*__expf(mo - M);
            mm = M;
        }
        if (t == 0){ fin[0] = mm; fin[1] = g_pgen[b] / ss; }
    }
    __syncthreads();
    const float M = fin[0], scale = fin[1];
    for (int v = t; v < V; v += 1024)
        out[(size_t)b*V + v] = __expf(row[v] - M) * scale;
}

// ---------------- copy-mechanism scatter ---------------------------------
__global__ void scatter_kernel(const int* __restrict__ enc_inputs,
                               float* __restrict__ out){
    const int idx = blockIdx.x*256 + threadIdx.x;
    if (idx >= MTOT) return;
    const int b = idx >> 11;
    const int tok = enc_inputs[idx];
    atomicAdd(&out[(size_t)b*V + tok], (1.f - g_pgen[b]) * g_attn[idx]);
}

// ---------------- launch --------------------------------------------------
extern "C" void kernel_launch(void* const* d_in, const int* in_sizes, int n_in,
                              void* d_out, int out_size) {
    const float* enc_out   = (const float*)d_in[0];
    const float* h0        = (const float*)d_in[1];
    const float* c0        = (const float*)d_in[2];
    const int*   dec_input = (const int*)  d_in[3];
    const int*   enc_inputs= (const int*)  d_in[4];
    const float* embed_tab = (const float*)d_in[5];
    const float* attn_wh_w = (const float*)d_in[6];
    const float* attn_wh_b = (const float*)d_in[7];
    const float* attn_ws_w = (const float*)d_in[8];
    const float* attn_ws_b = (const float*)d_in[9];
    const float* attn_v    = (const float*)d_in[10];
    const float* lstm_w_ih = (const float*)d_in[11];
    const float* lstm_w_hh = (const float*)d_in[12];
    const float* lstm_b_ih = (const float*)d_in[13];
    const float* lstm_b_hh = (const float*)d_in[14];
    const float* wh_vec    = (const float*)d_in[15];
    const float* ws_vec    = (const float*)d_in[16];
    const float* wx_vec    = (const float*)d_in[17];
    const float* v_w       = (const float*)d_in[18];
    const float* v_b       = (const float*)d_in[19];
    float* out = (float*)d_out;

    static bool attr_set = false;
    if (!attr_set){
        cudaFuncSetAttribute(energy_mma, cudaFuncAttributeMaxDynamicSharedMemorySize, EN_SMEM);
        attr_set = true;
    }

    // energy_mma kept as the 4th launch (ncu capture slot)
    conv_w_kernel<<<2048, 256>>>(attn_wh_w);
    wsapp_kernel<<<dim3(B, 64), 256>>>(h0, attn_ws_w, attn_ws_b, attn_wh_b);
    init_kernel<<<256, 256>>>(dec_input, embed_tab);
    energy_mma<<<dim3(H/NTILE, MTOT/MT), 256, EN_SMEM>>>(enc_out, attn_v);
    attn_softmax<<<B, 256>>>();
    context_kernel<<<dim3(B, 4, 4), 256>>>(enc_out);
    gates_gemm<<<dim3((4*H)/64, 4), 256>>>(h0, lstm_w_ih, lstm_w_hh);
    lstm_kernel<<<B, 512>>>(c0, lstm_b_ih, lstm_b_hh, wh_vec, ws_vec, wx_vec, out);
    logits_mma<<<(V + 127)/128, 256>>>(v_w, v_b);
    vocab_out_kernel<<<B, 1024>>>(out);
    scatter_kernel<<<(MTOT + 255)/256, 256>>>(enc_inputs, out);
}

// round 15
// speedup vs baseline: 4.3035x; 1.0463x over previous
#include <cuda_runtime.h>
#include <cuda_fp16.h>
#include <math.h>
#include <stdint.h>

#define B 64
#define S 2048
#define E 1024
#define H 512
#define EMBD 256
#define V 50257
#define MTOT (B*S)
#define NLBLK ((V + 127)/128)      // 393 logits CTAs

#define OUT_HT ((size_t)B*V)
#define OUT_CT (OUT_HT + (size_t)B*H)

// ---------------- device scratch (no allocations allowed) ----------------
__device__ float g_ws_app[B*H];
__device__ float g_energy4[4][MTOT];
__device__ float g_attn[MTOT];
__device__ float g_context[B*E];
__device__ float g_embed[B*EMBD];
__device__ float g_gates8[8][B*4*H];
__device__ float g_logits[(size_t)B*V];
__device__ float g_pgen[B];
__device__ float g_lmax[NLBLK][B];     // per-logits-CTA row max
__device__ float g_lsum[NLBLK][B];     // per-logits-CTA row sumexp
__device__ float g_vfin[B*2];          // [M, pgen/Z] per batch

__device__ __half g_w_h[H*E];          // attn_wh_w fp16
__device__ __half g_ht_hi[B*H];        // h_t fp16 hi
__device__ __half g_ht_lo[B*H];        // h_t fp16 lo

__device__ __forceinline__ float sigf(float x){ return 1.f/(1.f+__expf(-x)); }
__device__ __forceinline__ float ftanh(float x){
    x = fminf(fmaxf(x, -15.f), 15.f);
    float e2 = __expf(2.f*x);
    return (e2 - 1.f) / (e2 + 1.f);
}
__device__ __forceinline__ void online(float& m, float& s, float x){
    if (x > m){ s = s*__expf(m - x) + 1.f; m = x; }
    else        s += __expf(x - m);
}
__device__ __forceinline__ void online_merge(float& m, float& s, float mo, float so){
    float M = fmaxf(m, mo);
    s = s*__expf(m - M) + so*__expf(mo - M);
    m = M;
}

// ======================= portable PTX helpers =============================
__device__ __forceinline__ uint32_t smem_u32(const void* p){
    uint32_t a;
    asm("{ .reg .u64 t; cvta.to.shared.u64 t, %1; cvt.u32.u64 %0, t; }" : "=r"(a) : "l"(p));
    return a;
}
__device__ __forceinline__ void cp16(uint32_t dst, const void* src){
    asm volatile("cp.async.cg.shared.global [%0], [%1], 16;" :: "r"(dst), "l"(src));
}
__device__ __forceinline__ void cp_commit(){ asm volatile("cp.async.commit_group;" ::: "memory"); }
__device__ __forceinline__ void cp_wait0(){ asm volatile("cp.async.wait_group 0;" ::: "memory"); }

__device__ __forceinline__ void ldsm4(uint32_t* r, uint32_t addr){
    asm volatile("ldmatrix.sync.aligned.m8n8.x4.shared.b16 {%0,%1,%2,%3}, [%4];"
        : "=r"(r[0]), "=r"(r[1]), "=r"(r[2]), "=r"(r[3]) : "r"(addr));
}
__device__ __forceinline__ void mma_f16(float* c, const uint32_t* a, uint32_t b0, uint32_t b1){
    asm volatile("mma.sync.aligned.m16n8k16.row.col.f32.f16.f16.f32 "
        "{%0,%1,%2,%3}, {%4,%5,%6,%7}, {%8,%9}, {%0,%1,%2,%3};"
        : "+f"(c[0]), "+f"(c[1]), "+f"(c[2]), "+f"(c[3])
        : "r"(a[0]), "r"(a[1]), "r"(a[2]), "r"(a[3]), "r"(b0), "r"(b1));
}

// ---------------- fp16 conversion for attn weights ------------------------
__global__ void conv_w_kernel(const float* __restrict__ src){
    int i = blockIdx.x*256 + threadIdx.x;
    g_w_h[i] = __float2half(src[i]);
}

// ---------------- init: zero context + embedding lookup ------------------
__global__ void init_kernel(const int* __restrict__ dec_input,
                            const float* __restrict__ table){
    int i = blockIdx.x*256 + threadIdx.x;
    if (i < B*E) g_context[i] = 0.f;
    if (i < B*EMBD){
        int b = i >> 8, t = i & 255;
        g_embed[i] = table[(size_t)dec_input[b]*EMBD + t];
    }
}

// ---------------- ws_app ---------------------------------------------------
__global__ void wsapp_kernel(const float* __restrict__ h0,
                             const float* __restrict__ ws_w,
                             const float* __restrict__ ws_b,
                             const float* __restrict__ wh_b){
    __shared__ float hs[H];
    const int b = blockIdx.x, tid = threadIdx.x;
    for (int i = tid; i < H; i += 256) hs[i] = h0[b*H + i];
    __syncthreads();
    const int warp = tid >> 5, lane = tid & 31;
    const int n = blockIdx.y * 8 + warp;
    const float* wrow = ws_w + (size_t)n*H;
    float acc = 0.f;
    #pragma unroll
    for (int k = lane*4; k < H; k += 128){
        float4 w = *(const float4*)(wrow + k);
        acc += hs[k]*w.x + hs[k+1]*w.y + hs[k+2]*w.z + hs[k+3]*w.w;
    }
    #pragma unroll
    for (int o = 16; o > 0; o >>= 1) acc += __shfl_xor_sync(0xffffffffu, acc, o);
    if (lane == 0) g_ws_app[b*H + n] = acc + ws_b[n] + wh_b[n];
}

// ---------------- asymmetric fp16 2-product energy GEMM (frozen) ---------
#define MT 128
#define NTILE 128
#define KC 32
#define NCH (E/KC)
#define ROWB 80
#define ARRB (128*ROWB)
#define STG_BYTES (3*ARRB)
#define WS_OFF (2*STG_BYTES)
#define V_OFF  (WS_OFF + 512)
#define EN_SMEM (V_OFF + 512)

__global__ __launch_bounds__(256, 2) void energy_mma(
        const float* __restrict__ enc, const float* __restrict__ attn_v){
    extern __shared__ char sm[];
    const int tid  = threadIdx.x;
    const int lane = tid & 31, wid = tid >> 5;
    const int wm = wid & 3;
    const int wn = wid >> 2;
    const int n0 = blockIdx.x * NTILE;
    const int m0 = blockIdx.y * MT;
    const int b  = m0 >> 11;

    float* wsP = (float*)(sm + WS_OFF);
    float* vP  = (float*)(sm + V_OFF);
    for (int j = tid; j < NTILE; j += 256){
        wsP[j] = g_ws_app[b*H + n0 + j];
        vP[j]  = attn_v[n0 + j];
    }

    const uint32_t smb = smem_u32(sm);
    const __half* Bg = g_w_h + (size_t)n0*E;

    const int ar = tid >> 1;
    const int kh = tid & 1;
    const float* Abase = enc + (size_t)(m0 + ar)*E + kh*16;

    auto loadB = [&](int stage, int k0){
        uint32_t stg = smb + (stage&1)*STG_BYTES + 2*ARRB;
        #pragma unroll
        for (int it = 0; it < 2; it++){
            int f = tid + it*256;
            int r = f >> 2, j = f & 3;
            cp16(stg + r*ROWB + j*16, Bg + (size_t)r*E + k0 + j*8);
        }
        cp_commit();
    };

    float areg[16];
    auto loadA = [&](int k0){
        const float4* gp = (const float4*)(Abase + k0);
        #pragma unroll
        for (int q = 0; q < 4; q++){
            float4 v = gp[q];
            areg[q*4+0] = v.x; areg[q*4+1] = v.y; areg[q*4+2] = v.z; areg[q*4+3] = v.w;
        }
    };
    auto storeA = [&](int stage){
        uint32_t off0 = (stage&1)*STG_BYTES;
        __half hb[16], lb[16];
        #pragma unroll
        for (int q = 0; q < 16; q++){
            hb[q] = __float2half(areg[q]);
            lb[q] = __float2half(areg[q] - __half2float(hb[q]));
        }
        uint32_t off = off0 + (uint32_t)ar*ROWB + kh*32;
        *(uint4*)(sm + off)              = *(uint4*)&hb[0];
        *(uint4*)(sm + off + 16)         = *(uint4*)&hb[8];
        *(uint4*)(sm + ARRB + off)       = *(uint4*)&lb[0];
        *(uint4*)(sm + ARRB + off + 16)  = *(uint4*)&lb[8];
    };

    float c[2][8][4];
    #pragma unroll
    for (int t = 0; t < 2; t++)
        #pragma unroll
        for (int j = 0; j < 8; j++)
            #pragma unroll
            for (int q = 0; q < 4; q++) c[t][j][q] = 0.f;

    loadB(0, 0);
    loadA(0);
    storeA(0);
    loadA(KC);

    for (int i = 0; i < NCH; i++){
        cp_wait0();
        __syncthreads();
        if (i + 1 < NCH){
            loadB(i+1, (i+1)*KC);
            storeA(i+1);
            if (i + 2 < NCH) loadA((i+2)*KC);
        }

        const uint32_t stg = smb + (i&1)*STG_BYTES;
        const uint32_t A0 = stg, A1 = stg + ARRB, B0 = stg + 2*ARRB;

        #pragma unroll
        for (int kk = 0; kk < 2; kk++){
            uint32_t ah[2][4], al[2][4];
            #pragma unroll
            for (int t = 0; t < 2; t++){
                int row = wm*32 + t*16 + (lane & 15);
                uint32_t off = (uint32_t)row*ROWB + (lane >> 4)*16 + kk*32;
                ldsm4(ah[t], A0 + off);
                ldsm4(al[t], A1 + off);
            }
            #pragma unroll
            for (int p = 0; p < 4; p++){
                int row = wn*64 + p*16 + ((lane >> 4) & 1)*8 + (lane & 7);
                uint32_t off = (uint32_t)row*ROWB + ((lane >> 3) & 1)*16 + kk*32;
                uint32_t rh[4];
                ldsm4(rh, B0 + off);
                #pragma unroll
                for (int t = 0; t < 2; t++){
                    mma_f16(c[t][2*p],   ah[t], rh[0], rh[1]);
                    mma_f16(c[t][2*p],   al[t], rh[0], rh[1]);
                    mma_f16(c[t][2*p+1], ah[t], rh[2], rh[3]);
                    mma_f16(c[t][2*p+1], al[t], rh[2], rh[3]);
                }
            }
        }
    }

    float p4[4] = {0.f, 0.f, 0.f, 0.f};
    #pragma unroll
    for (int t = 0; t < 2; t++)
        #pragma unroll
        for (int j = 0; j < 8; j++)
            #pragma unroll
            for (int q = 0; q < 4; q++){
                int nloc = wn*64 + j*8 + (lane & 3)*2 + (q & 1);
                float x = c[t][j][q] + wsP[nloc];
                p4[t*2 + (q >> 1)] += ftanh(x) * vP[nloc];
            }
    #pragma unroll
    for (int q = 0; q < 4; q++){
        p4[q] += __shfl_xor_sync(0xffffffffu, p4[q], 1);
        p4[q] += __shfl_xor_sync(0xffffffffu, p4[q], 2);
    }
    __syncthreads();
    float* red = (float*)(sm);
    if ((lane & 3) == 0){
        int rloc = wm*32 + (lane >> 2);
        if (wn == 0){
            red[rloc]      = p4[0];
            red[rloc + 8]  = p4[1];
            red[rloc + 16] = p4[2];
            red[rloc + 24] = p4[3];
        }
    }
    __syncthreads();
    if (wn == 1 && (lane & 3) == 0){
        int rloc = wm*32 + (lane >> 2);
        g_energy4[blockIdx.x][m0 + rloc]      = red[rloc]      + p4[0];
        g_energy4[blockIdx.x][m0 + rloc + 8]  = red[rloc + 8]  + p4[1];
        g_energy4[blockIdx.x][m0 + rloc + 16] = red[rloc + 16] + p4[2];
        g_energy4[blockIdx.x][m0 + rloc + 24] = red[rloc + 24] + p4[3];
    }
}

// ---------------- softmax over S per batch -------------------------------
__global__ void attn_softmax(){
    const int b = blockIdx.x, t = threadIdx.x;
    __shared__ float red[8];
    float ev[8];
    float m = -1e30f;
    #pragma unroll
    for (int q = 0; q < 8; q++){
        int idx = b*S + q*256 + t;
        float v = g_energy4[0][idx] + g_energy4[1][idx] + g_energy4[2][idx] + g_energy4[3][idx];
        ev[q] = v;
        m = fmaxf(m, v);
    }
    #pragma unroll
    for (int o = 16; o > 0; o >>= 1) m = fmaxf(m, __shfl_xor_sync(0xffffffffu, m, o));
    if ((t & 31) == 0) red[t >> 5] = m;
    __syncthreads();
    if (t == 0){ float mm = red[0]; for (int i = 1; i < 8; i++) mm = fmaxf(mm, red[i]); red[0] = mm; }
    __syncthreads();
    m = red[0];
    __syncthreads();
    float s = 0.f;
    #pragma unroll
    for (int q = 0; q < 8; q++){ ev[q] = __expf(ev[q]-m); s += ev[q]; }
    #pragma unroll
    for (int o = 16; o > 0; o >>= 1) s += __shfl_xor_sync(0xffffffffu, s, o);
    if ((t & 31) == 0) red[t >> 5] = s;
    __syncthreads();
    if (t == 0){ float ss = 0.f; for (int i = 0; i < 8; i++) ss += red[i]; red[0] = ss; }
    __syncthreads();
    float inv = 1.f / red[0];
    #pragma unroll
    for (int q = 0; q < 8; q++) g_attn[b*S + q*256 + t] = ev[q] * inv;
}

// ---------------- context --------------------------------------------------
__global__ void context_kernel(const float* __restrict__ enc){
    const int b = blockIdx.x, ec = blockIdx.y, sc = blockIdx.z;
    __shared__ float a_s[512];
    const int t = threadIdx.x;
    for (int i = t; i < 512; i += 256) a_s[i] = g_attn[b*S + sc*512 + i];
    __syncthreads();
    const int e = ec*256 + t;
    const float* base = enc + ((size_t)b*S + sc*512)*E + e;
    float acc = 0.f;
    #pragma unroll 4
    for (int s = 0; s < 512; s++) acc = fmaf(a_s[s], base[(size_t)s*E], acc);
    atomicAdd(&g_context[b*E + e], acc);
}

// ---------------- LSTM gates GEMM (K-split x8) ---------------------------
__global__ __launch_bounds__(256) void gates_gemm(
        const float* __restrict__ h0,
        const float* __restrict__ w_ih,
        const float* __restrict__ w_hh){
    __shared__ float Xs[16][65];
    __shared__ float Ws[16][65];
    const int n0 = blockIdx.x * 64;
    const int ks = blockIdx.y;            // 0..7, K=224 each
    const int tid = threadIdx.x;
    const int tx = tid & 15, ty = tid >> 4;
    float acc[4][4];
    #pragma unroll
    for (int i = 0; i < 4; i++)
        #pragma unroll
        for (int j = 0; j < 4; j++) acc[i][j] = 0.f;

    for (int k0 = ks*224; k0 < (ks+1)*224; k0 += 16) {
        for (int i = tid; i < 64*16; i += 256){
            int m = i >> 4, kk = i & 15, k = k0 + kk;
            float xv;
            if (k < E)            xv = g_context[m*E + k];
            else if (k < E+EMBD)  xv = g_embed[m*EMBD + (k - E)];
            else                  xv = h0[m*H + (k - E - EMBD)];
            Xs[kk][m] = xv;
        }
        for (int i = tid; i < 64*16; i += 256){
            int nn = i >> 4, kk = i & 15, k = k0 + kk, n = n0 + nn;
            float wv = (k < E+EMBD) ? w_ih[(size_t)n*(E+EMBD) + k]
                                    : w_hh[(size_t)n*H + (k - E - EMBD)];
            Ws[kk][nn] = wv;
        }
        __syncthreads();
        #pragma unroll
        for (int kk = 0; kk < 16; kk++){
            float ra[4], rb[4];
            #pragma unroll
            for (int i = 0; i < 4; i++) ra[i] = Xs[kk][ty*4+i];
            #pragma unroll
            for (int j = 0; j < 4; j++) rb[j] = Ws[kk][tx*4+j];
            #pragma unroll
            for (int i = 0; i < 4; i++)
                #pragma unroll
                for (int j = 0; j < 4; j++) acc[i][j] = fmaf(ra[i], rb[j], acc[i][j]);
        }
        __syncthreads();
    }
    #pragma unroll
    for (int i = 0; i < 4; i++)
        #pragma unroll
        for (int j = 0; j < 4; j++){
            int m = ty*4+i, n = n0 + tx*4+j;
            g_gates8[ks][m*(4*H) + n] = acc[i][j];
        }
}

// ---------------- LSTM pointwise + p_gen (fused) -------------------------
__global__ void lstm_kernel(const float* __restrict__ c0,
                            const float* __restrict__ b_ih,
                            const float* __restrict__ b_hh,
                            const float* __restrict__ wh_vec,
                            const float* __restrict__ ws_vec,
                            const float* __restrict__ wx_vec,
                            float* __restrict__ out){
    __shared__ float red[16];
    const int b = blockIdx.x, h = threadIdx.x;
    const int base = b*(4*H);
    float gi = 0.f, gf = 0.f, gg = 0.f, go = 0.f;
    #pragma unroll
    for (int p = 0; p < 8; p++){
        const float* gp = g_gates8[p] + base;
        gi += gp[h];
        gf += gp[H + h];
        gg += gp[2*H + h];
        go += gp[3*H + h];
    }
    gi += b_ih[h]       + b_hh[h];
    gf += b_ih[H + h]   + b_hh[H + h];
    gg += b_ih[2*H + h] + b_hh[2*H + h];
    go += b_ih[3*H + h] + b_hh[3*H + h];
    float ig = sigf(gi);
    float fg = sigf(gf);
    float gv = tanhf(gg);
    float og = sigf(go);
    float c  = fg * c0[b*H + h] + ig * gv;
    float ht = og * tanhf(c);
    out[OUT_HT + b*H + h] = ht;
    out[OUT_CT + b*H + h] = c;
    __half hh = __float2half(ht);
    g_ht_hi[b*H + h] = hh;
    g_ht_lo[b*H + h] = __float2half(ht - __half2float(hh));

    float acc = ht * ws_vec[h];
    acc += g_context[b*E + h]       * wh_vec[h];
    acc += g_context[b*E + h + 512] * wh_vec[h + 512];
    if (h < EMBD) acc += g_embed[b*EMBD + h] * wx_vec[h];
    #pragma unroll
    for (int o = 16; o > 0; o >>= 1) acc += __shfl_xor_sync(0xffffffffu, acc, o);
    if ((h & 31) == 0) red[h >> 5] = acc;
    __syncthreads();
    if (h == 0){
        float s = 0.f;
        for (int i = 0; i < 16; i++) s += red[i];
        g_pgen[b] = sigf(s);
    }
}

// ---------------- logits HMMA + fused softmax partials -------------------
#define LKC 32
#define LCH (H/LKC)
#define LRB 80
#define LH_ARR (64*LRB)
#define LW_ARR (128*LRB)
#define LSTG (2*LH_ARR + LW_ARR)

__global__ __launch_bounds__(256) void logits_mma(
        const float* __restrict__ vw, const float* __restrict__ vb){
    __shared__ char sm2[2*LSTG];
    const int tid  = threadIdx.x;
    const int lane = tid & 31, wid = tid >> 5;
    const int wm = wid & 3;
    const int wn = wid >> 2;
    const int n0 = blockIdx.x * 128;
    const uint32_t smb = smem_u32(sm2);

    auto loadA_cp = [&](int i){
        uint32_t stg = smb + (i&1)*LSTG;
        int k0 = i*LKC;
        #pragma unroll
        for (int it = 0; it < 2; it++){
            int f = tid + it*256;
            int digit = f >> 8, idx = f & 255;
            int r = idx >> 2, j = idx & 3;
            const __half* src = (digit ? g_ht_lo : g_ht_hi) + r*H + k0 + j*8;
            cp16(stg + digit*LH_ARR + r*LRB + j*16, src);
        }
        cp_commit();
    };

    const int br = tid >> 1;
    const int bkh = tid & 1;
    int rg = n0 + br; if (rg >= V) rg = V - 1;
    const float* Bbase = vw + (size_t)rg*H + bkh*16;

    float breg[16];
    auto loadB = [&](int k0){
        const float4* gp = (const float4*)(Bbase + k0);
        #pragma unroll
        for (int q = 0; q < 4; q++){
            float4 v = gp[q];
            breg[q*4+0] = v.x; breg[q*4+1] = v.y; breg[q*4+2] = v.z; breg[q*4+3] = v.w;
        }
    };
    auto storeB = [&](int stage){
        __half hb[16];
        #pragma unroll
        for (int q = 0; q < 16; q++) hb[q] = __float2half(breg[q]);
        uint32_t off = (stage&1)*LSTG + 2*LH_ARR + (uint32_t)br*LRB + bkh*32;
        *(uint4*)(sm2 + off)      = *(uint4*)&hb[0];
        *(uint4*)(sm2 + off + 16) = *(uint4*)&hb[8];
    };

    float c[8][4];
    #pragma unroll
    for (int j = 0; j < 8; j++)
        #pragma unroll
        for (int q = 0; q < 4; q++) c[j][q] = 0.f;

    loadA_cp(0);
    loadB(0);
    storeB(0);
    loadB(LKC);

    for (int i = 0; i < LCH; i++){
        cp_wait0();
        __syncthreads();
        if (i + 1 < LCH){
            loadA_cp(i+1);
            storeB(i+1);
            if (i + 2 < LCH) loadB((i+2)*LKC);
        }

        const uint32_t stg = smb + (i&1)*LSTG;
        const uint32_t A0 = stg, A1 = stg + LH_ARR, B0 = stg + 2*LH_ARR;

        #pragma unroll
        for (int kk = 0; kk < 2; kk++){
            uint32_t ah[4], al[4];
            {
                int row = wm*16 + (lane & 15);
                uint32_t off = (uint32_t)row*LRB + (lane >> 4)*16 + kk*32;
                ldsm4(ah, A0 + off);
                ldsm4(al, A1 + off);
            }
            #pragma unroll
            for (int p = 0; p < 4; p++){
                int row = wn*64 + p*16 + ((lane >> 4) & 1)*8 + (lane & 7);
                uint32_t off = (uint32_t)row*LRB + ((lane >> 3) & 1)*16 + kk*32;
                uint32_t rh[4];
                ldsm4(rh, B0 + off);
                mma_f16(c[2*p],   ah, rh[0], rh[1]);
                mma_f16(c[2*p],   al, rh[0], rh[1]);
                mma_f16(c[2*p+1], ah, rh[2], rh[3]);
                mma_f16(c[2*p+1], al, rh[2], rh[3]);
            }
        }
    }

    // epilogue: write logits + per-row online (max, sumexp) partials
    float lm[2] = {-1e30f, -1e30f}, ls[2] = {0.f, 0.f};
    #pragma unroll
    for (int j = 0; j < 8; j++)
        #pragma unroll
        for (int q = 0; q < 4; q++){
            int t2 = q >> 1;
            int m = wm*16 + (lane >> 2) + t2*8;
            int v = n0 + wn*64 + j*8 + (lane & 3)*2 + (q & 1);
            float x = -1e30f;
            if (v < V){
                x = c[j][q] + vb[v];
                g_logits[(size_t)m*V + v] = x;
            }
            online(lm[t2], ls[t2], x);
        }
    // 4-lane combine (same row within warp)
    #pragma unroll
    for (int t2 = 0; t2 < 2; t2++){
        #pragma unroll
        for (int o = 1; o <= 2; o <<= 1){
            float mo = __shfl_xor_sync(0xffffffffu, lm[t2], o);
            float so = __shfl_xor_sync(0xffffffffu, ls[t2], o);
            online_merge(lm[t2], ls[t2], mo, so);
        }
    }
    __syncthreads();                      // smem free after MMA
    float* rm = (float*)sm2;              // 64 floats
    float* rs = rm + 64;
    if (wn == 0 && (lane & 3) == 0){
        #pragma unroll
        for (int t2 = 0; t2 < 2; t2++){
            int r = wm*16 + (lane >> 2) + t2*8;
            rm[r] = lm[t2];
            rs[r] = ls[t2];
        }
    }
    __syncthreads();
    if (wn == 1 && (lane & 3) == 0){
        #pragma unroll
        for (int t2 = 0; t2 < 2; t2++){
            int r = wm*16 + (lane >> 2) + t2*8;
            float M = lm[t2], Sx = ls[t2];
            online_merge(M, Sx, rm[r], rs[r]);
            g_lmax[blockIdx.x][r] = M;
            g_lsum[blockIdx.x][r] = Sx;
        }
    }
}

// ---------------- vocab reduce: combine per-CTA partials -----------------
__global__ void vocab_reduce(){
    const int b = blockIdx.x, t = threadIdx.x;   // 256 threads
    const int lane = t & 31, wrp = t >> 5;
    __shared__ float redm[8], reds[8];
    float m = -1e30f, s = 0.f;
    for (int blk = t; blk < NLBLK; blk += 256)
        online_merge(m, s, g_lmax[blk][b], g_lsum[blk][b]);
    #pragma unroll
    for (int o = 16; o > 0; o >>= 1){
        float mo = __shfl_xor_sync(0xffffffffu, m, o);
        float so = __shfl_xor_sync(0xffffffffu, s, o);
        online_merge(m, s, mo, so);
    }
    if (lane == 0){ redm[wrp] = m; reds[wrp] = s; }
    __syncthreads();
    if (t == 0){
        float M = redm[0], Sx = reds[0];
        for (int i = 1; i < 8; i++) online_merge(M, Sx, redm[i], reds[i]);
        g_vfin[b*2]     = M;
        g_vfin[b*2 + 1] = g_pgen[b] / Sx;
    }
}

// ---------------- vocab write (fully parallel) ---------------------------
#define VCHUNK 6283   // ceil(V/8)
__global__ void vocab_write(float* __restrict__ out){
    const int b = blockIdx.y;
    const float M = g_vfin[b*2], scale = g_vfin[b*2 + 1];
    const int v0 = blockIdx.x * VCHUNK;
    const int vend = min(v0 + VCHUNK, V);
    const float* row = g_logits + (size_t)b*V;
    for (int v = v0 + threadIdx.x; v < vend; v += 1024)
        out[(size_t)b*V + v] = __expf(row[v] - M) * scale;
}

// ---------------- copy-mechanism scatter ---------------------------------
__global__ void scatter_kernel(const int* __restrict__ enc_inputs,
                               float* __restrict__ out){
    const int idx = blockIdx.x*256 + threadIdx.x;
    if (idx >= MTOT) return;
    const int b = idx >> 11;
    const int tok = enc_inputs[idx];
    atomicAdd(&out[(size_t)b*V + tok], (1.f - g_pgen[b]) * g_attn[idx]);
}

// ---------------- launch --------------------------------------------------
extern "C" void kernel_launch(void* const* d_in, const int* in_sizes, int n_in,
                              void* d_out, int out_size) {
    const float* enc_out   = (const float*)d_in[0];
    const float* h0        = (const float*)d_in[1];
    const float* c0        = (const float*)d_in[2];
    const int*   dec_input = (const int*)  d_in[3];
    const int*   enc_inputs= (const int*)  d_in[4];
    const float* embed_tab = (const float*)d_in[5];
    const float* attn_wh_w = (const float*)d_in[6];
    const float* attn_wh_b = (const float*)d_in[7];
    const float* attn_ws_w = (const float*)d_in[8];
    const float* attn_ws_b = (const float*)d_in[9];
    const float* attn_v    = (const float*)d_in[10];
    const float* lstm_w_ih = (const float*)d_in[11];
    const float* lstm_w_hh = (const float*)d_in[12];
    const float* lstm_b_ih = (const float*)d_in[13];
    const float* lstm_b_hh = (const float*)d_in[14];
    const float* wh_vec    = (const float*)d_in[15];
    const float* ws_vec    = (const float*)d_in[16];
    const float* wx_vec    = (const float*)d_in[17];
    const float* v_w       = (const float*)d_in[18];
    const float* v_b       = (const float*)d_in[19];
    float* out = (float*)d_out;

    static bool attr_set = false;
    if (!attr_set){
        cudaFuncSetAttribute(energy_mma, cudaFuncAttributeMaxDynamicSharedMemorySize, EN_SMEM);
        attr_set = true;
    }

    // energy_mma kept as the 4th launch (ncu capture slot)
    conv_w_kernel<<<2048, 256>>>(attn_wh_w);
    wsapp_kernel<<<dim3(B, 64), 256>>>(h0, attn_ws_w, attn_ws_b, attn_wh_b);
    init_kernel<<<256, 256>>>(dec_input, embed_tab);
    energy_mma<<<dim3(H/NTILE, MTOT/MT), 256, EN_SMEM>>>(enc_out, attn_v);
    attn_softmax<<<B, 256>>>();
    context_kernel<<<dim3(B, 4, 4), 256>>>(enc_out);
    gates_gemm<<<dim3((4*H)/64, 8), 256>>>(h0, lstm_w_ih, lstm_w_hh);
    lstm_kernel<<<B, 512>>>(c0, lstm_b_ih, lstm_b_hh, wh_vec, ws_vec, wx_vec, out);
    logits_mma<<<NLBLK, 256>>>(v_w, v_b);
    vocab_reduce<<<B, 256>>>();
    vocab_write<<<dim3(8, B), 1024>>>(out);
    scatter_kernel<<<(MTOT + 255)/256, 256>>>(enc_inputs, out);
}